// round 2
// baseline (speedup 1.0000x reference)
#include <cuda_runtime.h>
#include <math.h>

// Problem constants
#define Bv 4
#define Nv 256
#define Dv 128
#define Hv 256
#define Kv 8
#define ROWS (Bv * Nv)   // 1024

// Scratch (static __device__ globals; no runtime allocation)
__device__ float Ug_buf[ROWS * Hv];       // s_i @ Wg1[0:128]   (per-row U for gate MLP)
__device__ float Ua_buf[ROWS * Hv];       // s_i @ Wa1[0:128]   (per-row U for att MLP)
__device__ float g_scores_buf[ROWS * Nv]; // dense gate scores

// ---------------------------------------------------------------------------
// Kernel 1: U = s @ W1_top for both MLPs. grid=128 blocks, 8 rows each.
// ---------------------------------------------------------------------------
__global__ __launch_bounds__(256) void u_kernel(
    const float* __restrict__ s,
    const float* __restrict__ Wg1,
    const float* __restrict__ Wa1)
{
    int r0 = blockIdx.x * 8;
    int tid = threadIdx.x;
    __shared__ float srows[8][Dv];
#pragma unroll
    for (int k = 0; k < 4; k++) {
        int ii = k * 256 + tid;           // 0..1023
        srows[ii >> 7][ii & 127] = s[r0 * Dv + ii];
    }
    __syncthreads();

    int h = tid;
    float accg[8], acca[8];
#pragma unroll
    for (int r = 0; r < 8; r++) { accg[r] = 0.f; acca[r] = 0.f; }
#pragma unroll 4
    for (int d = 0; d < Dv; d++) {
        float wg = Wg1[d * Hv + h];
        float wa = Wa1[d * Hv + h];
#pragma unroll
        for (int r = 0; r < 8; r++) {
            accg[r] = fmaf(srows[r][d], wg, accg[r]);
            acca[r] = fmaf(srows[r][d], wa, acca[r]);
        }
    }
#pragma unroll
    for (int r = 0; r < 8; r++) {
        Ug_buf[(r0 + r) * Hv + h] = accg[r];
        Ua_buf[(r0 + r) * Hv + h] = acca[r];
    }
}

// ---------------------------------------------------------------------------
// Kernel 2: dense fp32 gate scores.
// score[b,i,j] = relu( z + U_i + b1 ) . W2 + b2,
//   z[j,h] = sum_d s_j[d] * ( W_mid[d,h] + s_i[d]*W_bot[d,h] )
// grid = 1024 (one block per (b,i)), 256 threads (one per j).
// ---------------------------------------------------------------------------
__global__ __launch_bounds__(256) void gscore_kernel(
    const float* __restrict__ s,
    const float* __restrict__ W1,
    const float* __restrict__ b1,
    const float* __restrict__ W2,
    const float* __restrict__ b2,
    float* __restrict__ scores)
{
    __shared__ float sT[32][257];   // s_j chunk, transposed: sT[d][j]
    __shared__ float cs[32][64];    // coefficient tile c[d][h]
    __shared__ float sis[Dv];       // s_i
    __shared__ float us[Hv];        // U row
    __shared__ float b1s[Hv];
    __shared__ float w2s[Hv];

    int bi = blockIdx.x;            // b*256 + i
    int b  = bi >> 8;
    int tid = threadIdx.x;
    int j = tid;

    if (tid < Dv) sis[tid] = s[bi * Dv + tid];
    us[tid]  = Ug_buf[bi * Hv + tid];
    b1s[tid] = b1[tid];
    w2s[tid] = W2[tid];
    __syncthreads();

    float score = 0.f;
    for (int hc = 0; hc < 4; hc++) {
        float acc[64];
#pragma unroll
        for (int h = 0; h < 64; h++) acc[h] = 0.f;

        for (int dc = 0; dc < 4; dc++) {
            // load s_j chunk (transposed, padded)
#pragma unroll
            for (int k = 0; k < 32; k++) {
                int ii = k * 256 + tid;           // 0..8191
                int dd = ii & 31;
                int jj = ii >> 5;
                sT[dd][jj] = s[(b * Nv + jj) * Dv + dc * 32 + dd];
            }
            // build coefficient tile: c = W_mid + s_i * W_bot
#pragma unroll
            for (int k = 0; k < 8; k++) {
                int ii = k * 256 + tid;           // 0..2047
                int d = ii >> 6;
                int h = ii & 63;
                int drow = dc * 32 + d;
                float wm = W1[(Dv + drow) * Hv + hc * 64 + h];
                float wb = W1[(2 * Dv + drow) * Hv + hc * 64 + h];
                cs[d][h] = fmaf(sis[drow], wb, wm);
            }
            __syncthreads();

#pragma unroll
            for (int d = 0; d < 32; d++) {
                float p = sT[d][j];
                const float4* c4 = reinterpret_cast<const float4*>(&cs[d][0]);
#pragma unroll
                for (int h4 = 0; h4 < 16; h4++) {
                    float4 wv = c4[h4];
                    acc[h4 * 4 + 0] = fmaf(p, wv.x, acc[h4 * 4 + 0]);
                    acc[h4 * 4 + 1] = fmaf(p, wv.y, acc[h4 * 4 + 1]);
                    acc[h4 * 4 + 2] = fmaf(p, wv.z, acc[h4 * 4 + 2]);
                    acc[h4 * 4 + 3] = fmaf(p, wv.w, acc[h4 * 4 + 3]);
                }
            }
            __syncthreads();
        }
        // epilogue for this h chunk: bias + relu + dot with W2
#pragma unroll
        for (int h = 0; h < 64; h++) {
            float v = acc[h] + us[hc * 64 + h] + b1s[hc * 64 + h];
            v = fmaxf(v, 0.f);
            score = fmaf(v, w2s[hc * 64 + h], score);
        }
    }
    scores[bi * Nv + j] = score + b2[0];
}

// ---------------------------------------------------------------------------
// Kernel 3: zero gate + att regions of the output.
// ---------------------------------------------------------------------------
__global__ void zero_kernel(float* __restrict__ p, int n4)
{
    int idx = blockIdx.x * blockDim.x + threadIdx.x;
    if (idx < n4) reinterpret_cast<float4*>(p)[idx] = make_float4(0.f, 0.f, 0.f, 0.f);
}

// ---------------------------------------------------------------------------
// Kernel 4: per-row top-8, exact att logits at selected j only, softmax,
// write ctx / gate / att. grid = 256 blocks (4 rows each), 256 threads.
// ---------------------------------------------------------------------------
__global__ __launch_bounds__(256) void topk_att_kernel(
    const float* __restrict__ s,
    const float* __restrict__ Wa1,
    const float* __restrict__ ba1,
    const float* __restrict__ Wa2,
    const float* __restrict__ ba2,
    float* __restrict__ ctx,
    float* __restrict__ gate,
    float* __restrict__ att)
{
    int b  = blockIdx.x >> 6;
    int i0 = (blockIdx.x & 63) << 2;
    int tid = threadIdx.x;
    int lane = tid & 31;
    int wrp = tid >> 5;

    __shared__ float sc[4][Nv];
    __shared__ int   sel[4][Kv];
    __shared__ float si4[4][Dv];
    __shared__ float selS[4][Kv][Dv];
    __shared__ float ua4[4][Hv];
    __shared__ float ba1s[Hv];
    __shared__ float wa2s[Hv];
    __shared__ float part[4][Kv][8];
    __shared__ float logit[4][Kv];
    __shared__ float attw[4][Kv];

#pragma unroll
    for (int r = 0; r < 4; r++) {
        sc[r][tid]  = g_scores_buf[(b * Nv + i0 + r) * Nv + tid];
        ua4[r][tid] = Ua_buf[(b * Nv + i0 + r) * Hv + tid];
    }
    ba1s[tid] = ba1[tid];
    wa2s[tid] = Wa2[tid];
#pragma unroll
    for (int k = 0; k < 2; k++) {
        int ii = k * 256 + tid;           // 0..511
        int r = ii >> 7, d = ii & 127;
        si4[r][d] = s[(b * Nv + i0 + r) * Dv + d];
    }
    __syncthreads();

    // top-8 per row: warp r handles row r (tie -> lowest index, matching lax.top_k)
    if (wrp < 4) {
        for (int t = 0; t < Kv; t++) {
            float bv = -INFINITY; int bidx = Nv;
            for (int q = lane; q < Nv; q += 32) {
                float v = sc[wrp][q];
                if (v > bv || (v == bv && q < bidx)) { bv = v; bidx = q; }
            }
#pragma unroll
            for (int off = 16; off > 0; off >>= 1) {
                float ov = __shfl_down_sync(0xffffffffu, bv, off);
                int   oi = __shfl_down_sync(0xffffffffu, bidx, off);
                if (ov > bv || (ov == bv && oi < bidx)) { bv = ov; bidx = oi; }
            }
            bidx = __shfl_sync(0xffffffffu, bidx, 0);
            if (lane == 0) { sel[wrp][t] = bidx; sc[wrp][bidx] = -INFINITY; }
            __syncwarp();
        }
    }
    __syncthreads();

    // gather selected s_j rows
#pragma unroll
    for (int k = 0; k < 16; k++) {
        int ii = k * 256 + tid;           // 0..4095
        int r = ii >> 10, jj = (ii >> 7) & 7, d = ii & 127;
        selS[r][jj][d] = s[(b * Nv + sel[r][jj]) * Dv + d];
    }
    __syncthreads();

    // exact att-MLP hidden at selected pairs; thread owns hidden index h = tid
    float acc[4][Kv];
#pragma unroll
    for (int r = 0; r < 4; r++)
#pragma unroll
        for (int jj = 0; jj < Kv; jj++) acc[r][jj] = 0.f;

    int h = tid;
#pragma unroll 4
    for (int d = 0; d < Dv; d++) {
        float wm = Wa1[(Dv + d) * Hv + h];
        float wb = Wa1[(2 * Dv + d) * Hv + h];
#pragma unroll
        for (int r = 0; r < 4; r++) {
            float c = fmaf(si4[r][d], wb, wm);
#pragma unroll
            for (int jj = 0; jj < Kv; jj++)
                acc[r][jj] = fmaf(selS[r][jj][d], c, acc[r][jj]);
        }
    }

    // relu + dot W2, block-reduce over h
#pragma unroll
    for (int r = 0; r < 4; r++) {
#pragma unroll
        for (int jj = 0; jj < Kv; jj++) {
            float v = acc[r][jj] + ua4[r][h] + ba1s[h];
            v = fmaxf(v, 0.f) * wa2s[h];
#pragma unroll
            for (int off = 16; off > 0; off >>= 1)
                v += __shfl_down_sync(0xffffffffu, v, off);
            if (lane == 0) part[r][jj][wrp] = v;
        }
    }
    __syncthreads();
    if (tid < 32) {
        int r = tid >> 3, jj = tid & 7;
        float sum = 0.f;
#pragma unroll
        for (int w8 = 0; w8 < 8; w8++) sum += part[r][jj][w8];
        logit[r][jj] = sum + ba2[0];
    }
    __syncthreads();
    if (tid < 4) {
        float m = -INFINITY;
#pragma unroll
        for (int jj = 0; jj < Kv; jj++) m = fmaxf(m, logit[tid][jj]);
        float e[Kv], ssum = 0.f;
#pragma unroll
        for (int jj = 0; jj < Kv; jj++) { e[jj] = expf(logit[tid][jj] - m); ssum += e[jj]; }
#pragma unroll
        for (int jj = 0; jj < Kv; jj++) attw[tid][jj] = e[jj] / ssum;
    }
    __syncthreads();

    // write gate + att at selected positions
    if (tid < 32) {
        int r = tid >> 3, jj = tid & 7;
        int i = i0 + r, js = sel[r][jj];
        gate[(b * Nv + i) * Nv + js] = 1.0f;
        att [(b * Nv + i) * Nv + js] = attw[r][jj];
    }
    // ctx[b,i,d] = sum_j attw * s_j[d]
    if (tid < Dv) {
        int d = tid;
#pragma unroll
        for (int r = 0; r < 4; r++) {
            float cv = 0.f;
#pragma unroll
            for (int jj = 0; jj < Kv; jj++)
                cv = fmaf(attw[r][jj], selS[r][jj][d], cv);
            ctx[(b * Nv + i0 + r) * Dv + d] = cv;
        }
    }
}

// ---------------------------------------------------------------------------
extern "C" void kernel_launch(void* const* d_in, const int* in_sizes, int n_in,
                              void* d_out, int out_size)
{
    const float* s   = (const float*)d_in[0];
    const float* Wg1 = (const float*)d_in[1];
    const float* bg1 = (const float*)d_in[2];
    const float* Wg2 = (const float*)d_in[3];
    const float* bg2 = (const float*)d_in[4];
    const float* Wa1 = (const float*)d_in[5];
    const float* ba1 = (const float*)d_in[6];
    const float* Wa2 = (const float*)d_in[7];
    const float* ba2 = (const float*)d_in[8];

    float* out  = (float*)d_out;
    float* ctx  = out;                               // B*N*D  = 131072
    float* gate = out + Bv * Nv * Dv;                // B*N*N  = 262144
    float* att  = gate + Bv * Nv * Nv;               // B*N*N  = 262144

    float* g_scores; cudaGetSymbolAddress((void**)&g_scores, g_scores_buf);

    // zero gate + att (ctx fully written by topk_att_kernel)
    int n4 = (2 * Bv * Nv * Nv) / 4;                 // 131072 float4s
    zero_kernel<<<(n4 + 255) / 256, 256>>>(gate, n4);

    u_kernel<<<ROWS / 8, 256>>>(s, Wg1, Wa1);
    gscore_kernel<<<ROWS, 256>>>(s, Wg1, bg1, Wg2, bg2, g_scores);
    topk_att_kernel<<<ROWS / 4, 256>>>(s, Wa1, ba1, Wa2, ba2, ctx, gate, att);
}

// round 3
// speedup vs baseline: 3.3429x; 3.3429x over previous
#include <cuda_runtime.h>
#include <cuda_bf16.h>
#include <math.h>

// Problem constants
#define Bv 4
#define Nv 256
#define Dv 128
#define Hv 256
#define Kv 8
#define Cv 16               // candidate count for exact rescore
#define ROWS (Bv * Nv)      // 1024

// Scratch (static __device__ globals; no runtime allocation)
__device__ float Ug_buf[ROWS * Hv];            // s_i @ Wg1_top
__device__ float Ua_buf[ROWS * Hv];            // s_i @ Wa1_top
__device__ float g_scores_buf[ROWS * Nv];      // approx gate scores (bf16 MMA)
__device__ __nv_bfloat16 s_bf16_buf[ROWS * Dv];

// ---------------------------------------------------------------------------
// Kernel 1: U = s @ W1_top for both MLPs + bf16 copy of s.
// ---------------------------------------------------------------------------
__global__ __launch_bounds__(256) void u_kernel(
    const float* __restrict__ s,
    const float* __restrict__ Wg1,
    const float* __restrict__ Wa1)
{
    int r0 = blockIdx.x * 8;
    int tid = threadIdx.x;
    __shared__ float srows[8][Dv];
#pragma unroll
    for (int k = 0; k < 4; k++) {
        int ii = k * 256 + tid;           // 0..1023
        float v = s[r0 * Dv + ii];
        srows[ii >> 7][ii & 127] = v;
        s_bf16_buf[r0 * Dv + ii] = __float2bfloat16(v);
    }
    __syncthreads();

    int h = tid;
    float accg[8], acca[8];
#pragma unroll
    for (int r = 0; r < 8; r++) { accg[r] = 0.f; acca[r] = 0.f; }
#pragma unroll 4
    for (int d = 0; d < Dv; d++) {
        float wg = Wg1[d * Hv + h];
        float wa = Wa1[d * Hv + h];
#pragma unroll
        for (int r = 0; r < 8; r++) {
            accg[r] = fmaf(srows[r][d], wg, accg[r]);
            acca[r] = fmaf(srows[r][d], wa, acca[r]);
        }
    }
#pragma unroll
    for (int r = 0; r < 8; r++) {
        Ug_buf[(r0 + r) * Hv + h] = accg[r];
        Ua_buf[(r0 + r) * Hv + h] = acca[r];
    }
}

// ---------------------------------------------------------------------------
// MMA helpers
// ---------------------------------------------------------------------------
__device__ __forceinline__ void ldsm4(unsigned* r, unsigned addr) {
    asm volatile("ldmatrix.sync.aligned.m8n8.x4.shared.b16 {%0,%1,%2,%3}, [%4];"
                 : "=r"(r[0]), "=r"(r[1]), "=r"(r[2]), "=r"(r[3]) : "r"(addr));
}
__device__ __forceinline__ void ldsm4t(unsigned* r, unsigned addr) {
    asm volatile("ldmatrix.sync.aligned.m8n8.x4.trans.shared.b16 {%0,%1,%2,%3}, [%4];"
                 : "=r"(r[0]), "=r"(r[1]), "=r"(r[2]), "=r"(r[3]) : "r"(addr));
}
__device__ __forceinline__ void mma16816(float* d, const unsigned* a, unsigned b0, unsigned b1) {
    asm volatile("mma.sync.aligned.m16n8k16.row.col.f32.bf16.bf16.f32 "
                 "{%0,%1,%2,%3}, {%4,%5,%6,%7}, {%8,%9}, {%0,%1,%2,%3};"
                 : "+f"(d[0]), "+f"(d[1]), "+f"(d[2]), "+f"(d[3])
                 : "r"(a[0]), "r"(a[1]), "r"(a[2]), "r"(a[3]), "r"(b0), "r"(b1));
}

// ---------------------------------------------------------------------------
// Kernel 2: approx gate scores via bf16 tensor-core GEMM.
// One block per (b,i): z = s_b @ c_i, c_i[d,h] = Wm[d,h] + s_i[d]*Wb[d,h];
// score[j] = sum_h relu(z[j,h] + U_i[h] + b1[h]) * W2[h] + b2.
// grid=1024, 256 threads (8 warps as 4m x 2n over M=256, N-chunk=64).
// ---------------------------------------------------------------------------
#define SJ 136   // padded bf16 stride for s tile (row = 272B)
#define CH 72    // padded bf16 stride for c tile (row = 144B)
#define OFS_C   69632
#define OFS_SC  88064
#define OFS_UB  89088
#define OFS_W2  90112
#define OFS_SI  91136
#define GSC_SMEM 92160

__global__ __launch_bounds__(256, 2) void gscore_mma_kernel(
    const float* __restrict__ s,
    const float* __restrict__ W1,
    const float* __restrict__ b1,
    const float* __restrict__ W2,
    const float* __restrict__ b2,
    float* __restrict__ scores)
{
    extern __shared__ unsigned char dynsm[];
    __nv_bfloat16* s_sm = (__nv_bfloat16*)dynsm;
    __nv_bfloat16* c_sm = (__nv_bfloat16*)(dynsm + OFS_C);
    float* score_sm = (float*)(dynsm + OFS_SC);
    float* ub_sm    = (float*)(dynsm + OFS_UB);
    float* w2_sm    = (float*)(dynsm + OFS_W2);
    float* si_sm    = (float*)(dynsm + OFS_SI);

    int bi = blockIdx.x;
    int b  = bi >> 8;
    int tid = threadIdx.x;
    int lane = tid & 31;
    int warp = tid >> 5;

    score_sm[tid] = 0.f;
    ub_sm[tid] = Ug_buf[bi * Hv + tid] + b1[tid];
    w2_sm[tid] = W2[tid];
    if (tid < Dv) si_sm[tid] = s[bi * Dv + tid];

    // copy s_b (bf16) into padded smem, 16B chunks
    {
        const uint4* src = (const uint4*)(s_bf16_buf + b * Nv * Dv);
#pragma unroll
        for (int k = 0; k < 16; k++) {
            int t = k * 256 + tid;            // 0..4095
            int row = t >> 4;
            int c8  = t & 15;
            *(uint4*)((char*)s_sm + row * 272 + c8 * 16) = src[t];
        }
    }
    __syncthreads();

    const unsigned sbase = (unsigned)__cvta_generic_to_shared(s_sm);
    const unsigned cbase = (unsigned)__cvta_generic_to_shared(c_sm);
    int wm = (warp & 3) * 64;
    int wn = (warp >> 2) * 32;
    int aRow = wm + (lane & 15);
    int aColB = ((lane >> 4) << 3) * 2;       // bytes
    int bK   = lane & 15;
    int bH   = wn + ((lane >> 4) << 3);

    for (int hc = 0; hc < 4; hc++) {
        // build c chunk [128][64] in bf16
#pragma unroll
        for (int k = 0; k < 32; k++) {
            int t = k * 256 + tid;            // 0..8191
            int d = t >> 6;
            int h = t & 63;
            int H = hc * 64 + h;
            float wmv = W1[(Dv + d) * Hv + H];
            float wbv = W1[(2 * Dv + d) * Hv + H];
            c_sm[d * CH + h] = __float2bfloat16(fmaf(si_sm[d], wbv, wmv));
        }
        __syncthreads();

        float acc[16][4];
#pragma unroll
        for (int q = 0; q < 16; q++) { acc[q][0]=0.f; acc[q][1]=0.f; acc[q][2]=0.f; acc[q][3]=0.f; }

#pragma unroll
        for (int ks = 0; ks < 8; ks++) {
            unsigned a[4][4], bq[2][4];
#pragma unroll
            for (int mt = 0; mt < 4; mt++) {
                unsigned addr = sbase + (unsigned)((aRow + mt * 16) * (SJ * 2) + ks * 32) + aColB;
                ldsm4(a[mt], addr);
            }
#pragma unroll
            for (int nt = 0; nt < 2; nt++) {
                unsigned addr = cbase + (unsigned)((ks * 16 + bK) * (CH * 2) + (bH + nt * 16) * 2);
                ldsm4t(bq[nt], addr);
            }
#pragma unroll
            for (int mt = 0; mt < 4; mt++)
#pragma unroll
                for (int n8 = 0; n8 < 4; n8++)
                    mma16816(acc[mt * 4 + n8], a[mt], bq[n8 >> 1][(n8 & 1) * 2], bq[n8 >> 1][(n8 & 1) * 2 + 1]);
        }

        // epilogue: relu + dot W2, reduce over quad, accumulate into score_sm
        int rr = wm + (lane >> 2);
        int hb = hc * 64 + wn + (lane & 3) * 2;
#pragma unroll
        for (int mt = 0; mt < 4; mt++) {
            float p0 = 0.f, p1 = 0.f;
#pragma unroll
            for (int n8 = 0; n8 < 4; n8++) {
                int h0 = hb + n8 * 8;
                float u0 = ub_sm[h0], u1 = ub_sm[h0 + 1];
                float w0 = w2_sm[h0], w1 = w2_sm[h0 + 1];
                const float* A = acc[mt * 4 + n8];
                p0 = fmaf(fmaxf(A[0] + u0, 0.f), w0, p0);
                p0 = fmaf(fmaxf(A[1] + u1, 0.f), w1, p0);
                p1 = fmaf(fmaxf(A[2] + u0, 0.f), w0, p1);
                p1 = fmaf(fmaxf(A[3] + u1, 0.f), w1, p1);
            }
            p0 += __shfl_xor_sync(0xffffffffu, p0, 1);
            p0 += __shfl_xor_sync(0xffffffffu, p0, 2);
            p1 += __shfl_xor_sync(0xffffffffu, p1, 1);
            p1 += __shfl_xor_sync(0xffffffffu, p1, 2);
            if ((lane & 3) == 0) {
                atomicAdd(&score_sm[rr + mt * 16], p0);
                atomicAdd(&score_sm[rr + mt * 16 + 8], p1);
            }
        }
        __syncthreads();
    }
    scores[bi * Nv + tid] = score_sm[tid] + b2[0];
}

// ---------------------------------------------------------------------------
// Kernel 3: zero gate + att regions of the output.
// ---------------------------------------------------------------------------
__global__ void zero_kernel(float* __restrict__ p, int n4)
{
    int idx = blockIdx.x * blockDim.x + threadIdx.x;
    if (idx < n4) reinterpret_cast<float4*>(p)[idx] = make_float4(0.f, 0.f, 0.f, 0.f);
}

// ---------------------------------------------------------------------------
// Kernel 4: approx top-16 -> exact fp32 rescore -> exact top-8 -> exact att.
// grid = 512 blocks (2 rows each), 256 threads.
// ---------------------------------------------------------------------------
__global__ __launch_bounds__(256) void topk_att_kernel(
    const float* __restrict__ s,
    const float* __restrict__ Wg1,
    const float* __restrict__ bg1,
    const float* __restrict__ Wg2,
    const float* __restrict__ bg2,
    const float* __restrict__ Wa1,
    const float* __restrict__ ba1,
    const float* __restrict__ Wa2,
    const float* __restrict__ ba2,
    float* __restrict__ ctx,
    float* __restrict__ gate,
    float* __restrict__ att)
{
    int b  = blockIdx.x >> 7;
    int i0 = (blockIdx.x & 127) << 1;
    int tid = threadIdx.x;
    int lane = tid & 31;
    int warp = tid >> 5;

    __shared__ float sc[2][Nv];
    __shared__ int   sel[2][Cv];
    __shared__ float si2[2][Dv];
    __shared__ float selS[2][Cv][Dv];
    __shared__ float ug2[2][Hv];
    __shared__ float ua2[2][Hv];
    __shared__ float bg1s[Hv], wg2s[Hv], ba1s[Hv], wa2s[Hv];
    __shared__ float part[2][Cv][8];
    __shared__ float exacts[2][Cv];
    __shared__ int   fsel[2][Kv];
    __shared__ int   fj[2][Kv];
    __shared__ float logit[2][Kv];
    __shared__ float attw[2][Kv];

#pragma unroll
    for (int r = 0; r < 2; r++) {
        sc[r][tid]  = g_scores_buf[(b * Nv + i0 + r) * Nv + tid];
        ug2[r][tid] = Ug_buf[(b * Nv + i0 + r) * Hv + tid];
        ua2[r][tid] = Ua_buf[(b * Nv + i0 + r) * Hv + tid];
    }
    bg1s[tid] = bg1[tid];
    wg2s[tid] = Wg2[tid];
    ba1s[tid] = ba1[tid];
    wa2s[tid] = Wa2[tid];
    {
        int r = tid >> 7, d = tid & 127;
        si2[r][d] = s[(b * Nv + i0 + r) * Dv + d];
    }
    __syncthreads();

    // approx top-16 per row (warps 0,1)
    if (warp < 2) {
        int r = warp;
        for (int t = 0; t < Cv; t++) {
            float bv = -INFINITY; int bidx = Nv;
#pragma unroll
            for (int k = 0; k < 8; k++) {
                int q = k * 32 + lane;
                float v = sc[r][q];
                if (v > bv || (v == bv && q < bidx)) { bv = v; bidx = q; }
            }
#pragma unroll
            for (int off = 16; off > 0; off >>= 1) {
                float ov = __shfl_down_sync(0xffffffffu, bv, off);
                int   oi = __shfl_down_sync(0xffffffffu, bidx, off);
                if (ov > bv || (ov == bv && oi < bidx)) { bv = ov; bidx = oi; }
            }
            bidx = __shfl_sync(0xffffffffu, bidx, 0);
            if (lane == 0) { sel[r][t] = bidx; sc[r][bidx] = -INFINITY; }
            __syncwarp();
        }
    }
    __syncthreads();

    // gather candidate s_j rows: 2*16*128 = 4096 floats
#pragma unroll
    for (int k = 0; k < 16; k++) {
        int ii = k * 256 + tid;
        int r = ii >> 11, c = (ii >> 7) & 15, d = ii & 127;
        selS[r][c][d] = s[(b * Nv + sel[r][c]) * Dv + d];
    }
    __syncthreads();

    // exact fp32 gate rescore of 16 candidates; thread owns hidden h = tid
    int h = tid;
    float accg[2][Cv];
#pragma unroll
    for (int r = 0; r < 2; r++)
#pragma unroll
        for (int c = 0; c < Cv; c++) accg[r][c] = 0.f;

#pragma unroll 2
    for (int d = 0; d < Dv; d++) {
        float wm = Wg1[(Dv + d) * Hv + h];
        float wb = Wg1[(2 * Dv + d) * Hv + h];
#pragma unroll
        for (int r = 0; r < 2; r++) {
            float c = fmaf(si2[r][d], wb, wm);
#pragma unroll
            for (int t = 0; t < Cv; t++)
                accg[r][t] = fmaf(selS[r][t][d], c, accg[r][t]);
        }
    }
#pragma unroll
    for (int r = 0; r < 2; r++) {
#pragma unroll
        for (int t = 0; t < Cv; t++) {
            float v = fmaxf(accg[r][t] + ug2[r][h] + bg1s[h], 0.f) * wg2s[h];
#pragma unroll
            for (int off = 16; off > 0; off >>= 1)
                v += __shfl_xor_sync(0xffffffffu, v, off);
            if (lane == 0) part[r][t][warp] = v;
        }
    }
    __syncthreads();
    if (tid < 32) {
        int r = tid >> 4, t = tid & 15;
        float sSum = 0.f;
#pragma unroll
        for (int w8 = 0; w8 < 8; w8++) sSum += part[r][t][w8];
        exacts[r][t] = sSum + bg2[0];
    }
    __syncthreads();

    // exact top-8 among 16 candidates (tie -> lowest original j)
    if (warp < 2) {
        int r = warp;
        float v = (lane < Cv) ? exacts[r][lane] : -INFINITY;
        int jj  = (lane < Cv) ? sel[r][lane] : (1 << 30);
        int cc  = lane;
        for (int t = 0; t < Kv; t++) {
            float bv = v; int bj = jj; int bc = cc;
#pragma unroll
            for (int off = 16; off > 0; off >>= 1) {
                float ov = __shfl_down_sync(0xffffffffu, bv, off);
                int   oj = __shfl_down_sync(0xffffffffu, bj, off);
                int   oc = __shfl_down_sync(0xffffffffu, bc, off);
                if (ov > bv || (ov == bv && oj < bj)) { bv = ov; bj = oj; bc = oc; }
            }
            bc = __shfl_sync(0xffffffffu, bc, 0);
            bj = __shfl_sync(0xffffffffu, bj, 0);
            if (lane == 0) { fsel[r][t] = bc; fj[r][t] = bj; }
            if (cc == bc) v = -INFINITY;
        }
    }
    __syncthreads();

    // exact att MLP at final 8
    int cof[2][Kv];
#pragma unroll
    for (int r = 0; r < 2; r++)
#pragma unroll
        for (int t = 0; t < Kv; t++) cof[r][t] = fsel[r][t];

    float acca[2][Kv];
#pragma unroll
    for (int r = 0; r < 2; r++)
#pragma unroll
        for (int t = 0; t < Kv; t++) acca[r][t] = 0.f;

#pragma unroll 2
    for (int d = 0; d < Dv; d++) {
        float wm = Wa1[(Dv + d) * Hv + h];
        float wb = Wa1[(2 * Dv + d) * Hv + h];
#pragma unroll
        for (int r = 0; r < 2; r++) {
            float c = fmaf(si2[r][d], wb, wm);
#pragma unroll
            for (int t = 0; t < Kv; t++)
                acca[r][t] = fmaf(selS[r][cof[r][t]][d], c, acca[r][t]);
        }
    }
#pragma unroll
    for (int r = 0; r < 2; r++) {
#pragma unroll
        for (int t = 0; t < Kv; t++) {
            float v = fmaxf(acca[r][t] + ua2[r][h] + ba1s[h], 0.f) * wa2s[h];
#pragma unroll
            for (int off = 16; off > 0; off >>= 1)
                v += __shfl_xor_sync(0xffffffffu, v, off);
            if (lane == 0) part[r][t][warp] = v;
        }
    }
    __syncthreads();
    if (tid < 16) {
        int r = tid >> 3, t = tid & 7;
        float sSum = 0.f;
#pragma unroll
        for (int w8 = 0; w8 < 8; w8++) sSum += part[r][t][w8];
        logit[r][t] = sSum + ba2[0];
    }
    __syncthreads();
    if (tid < 2) {
        float m = -INFINITY;
#pragma unroll
        for (int t = 0; t < Kv; t++) m = fmaxf(m, logit[tid][t]);
        float e[Kv], ssum = 0.f;
#pragma unroll
        for (int t = 0; t < Kv; t++) { e[t] = expf(logit[tid][t] - m); ssum += e[t]; }
#pragma unroll
        for (int t = 0; t < Kv; t++) attw[tid][t] = e[t] / ssum;
    }
    __syncthreads();

    if (tid < 16) {
        int r = tid >> 3, t = tid & 7;
        int i = i0 + r, js = fj[r][t];
        gate[(b * Nv + i) * Nv + js] = 1.0f;
        att [(b * Nv + i) * Nv + js] = attw[r][t];
    }
    if (tid < Dv) {
        int d = tid;
#pragma unroll
        for (int r = 0; r < 2; r++) {
            float cv = 0.f;
#pragma unroll
            for (int t = 0; t < Kv; t++)
                cv = fmaf(attw[r][t], selS[r][cof[r][t]][d], cv);
            ctx[(b * Nv + i0 + r) * Dv + d] = cv;
        }
    }
}

// ---------------------------------------------------------------------------
extern "C" void kernel_launch(void* const* d_in, const int* in_sizes, int n_in,
                              void* d_out, int out_size)
{
    const float* s   = (const float*)d_in[0];
    const float* Wg1 = (const float*)d_in[1];
    const float* bg1 = (const float*)d_in[2];
    const float* Wg2 = (const float*)d_in[3];
    const float* bg2 = (const float*)d_in[4];
    const float* Wa1 = (const float*)d_in[5];
    const float* ba1 = (const float*)d_in[6];
    const float* Wa2 = (const float*)d_in[7];
    const float* ba2 = (const float*)d_in[8];

    float* out  = (float*)d_out;
    float* ctx  = out;
    float* gate = out + Bv * Nv * Dv;
    float* att  = gate + Bv * Nv * Nv;

    float* g_scores; cudaGetSymbolAddress((void**)&g_scores, g_scores_buf);

    cudaFuncSetAttribute(gscore_mma_kernel,
                         cudaFuncAttributeMaxDynamicSharedMemorySize, GSC_SMEM);

    int n4 = (2 * Bv * Nv * Nv) / 4;
    zero_kernel<<<(n4 + 255) / 256, 256>>>(gate, n4);

    u_kernel<<<ROWS / 8, 256>>>(s, Wg1, Wa1);
    gscore_mma_kernel<<<ROWS, 256, GSC_SMEM>>>(s, Wg1, bg1, Wg2, bg2, g_scores);
    topk_att_kernel<<<ROWS / 2, 256>>>(s, Wg1, bg1, Wg2, bg2,
                                       Wa1, ba1, Wa2, ba2, ctx, gate, att);
}

// round 4
// speedup vs baseline: 3.7637x; 1.1259x over previous
#include <cuda_runtime.h>
#include <cuda_bf16.h>
#include <math.h>

// Problem constants
#define Bv 4
#define Nv 256
#define Dv 128
#define Hv 256
#define Kv 8
#define Cv 12               // candidate count for exact rescore
#define ROWS (Bv * Nv)      // 1024

// Scratch (static __device__ globals; no runtime allocation)
__device__ float Ug_buf[ROWS * Hv];            // s_i @ Wg1_top
__device__ float Ua_buf[ROWS * Hv];            // s_i @ Wa1_top
__device__ float g_scores_buf[ROWS * Nv];      // approx gate scores (bf16 MMA)
__device__ __nv_bfloat16 s_bf16_buf[ROWS * Dv];

// ---------------------------------------------------------------------------
// f32x2 packed helpers (sm_103a dual fp32 pipe)
// ---------------------------------------------------------------------------
__device__ __forceinline__ void ffma2(unsigned long long& d,
                                      unsigned long long a,
                                      unsigned long long b) {
    asm("fma.rn.f32x2 %0, %1, %2, %0;" : "+l"(d) : "l"(a), "l"(b));
}
__device__ __forceinline__ unsigned long long pack2(float x, float y) {
    unsigned long long r;
    asm("mov.b64 %0, {%1, %2};" : "=l"(r) : "f"(x), "f"(y));
    return r;
}
__device__ __forceinline__ float2 unpack2(unsigned long long v) {
    float2 r;
    asm("mov.b64 {%0, %1}, %2;" : "=f"(r.x), "=f"(r.y) : "l"(v));
    return r;
}

// ---------------------------------------------------------------------------
// Kernel 1: U = s @ W1_top for both MLPs + bf16 copy of s.
// ---------------------------------------------------------------------------
__global__ __launch_bounds__(256) void u_kernel(
    const float* __restrict__ s,
    const float* __restrict__ Wg1,
    const float* __restrict__ Wa1)
{
    int r0 = blockIdx.x * 8;
    int tid = threadIdx.x;
    __shared__ float srows[8][Dv];
#pragma unroll
    for (int k = 0; k < 4; k++) {
        int ii = k * 256 + tid;           // 0..1023
        float v = s[r0 * Dv + ii];
        srows[ii >> 7][ii & 127] = v;
        s_bf16_buf[r0 * Dv + ii] = __float2bfloat16(v);
    }
    __syncthreads();

    int h = tid;
    float accg[8], acca[8];
#pragma unroll
    for (int r = 0; r < 8; r++) { accg[r] = 0.f; acca[r] = 0.f; }
#pragma unroll 4
    for (int d = 0; d < Dv; d++) {
        float wg = Wg1[d * Hv + h];
        float wa = Wa1[d * Hv + h];
#pragma unroll
        for (int r = 0; r < 8; r++) {
            accg[r] = fmaf(srows[r][d], wg, accg[r]);
            acca[r] = fmaf(srows[r][d], wa, acca[r]);
        }
    }
#pragma unroll
    for (int r = 0; r < 8; r++) {
        Ug_buf[(r0 + r) * Hv + h] = accg[r];
        Ua_buf[(r0 + r) * Hv + h] = acca[r];
    }
}

// ---------------------------------------------------------------------------
// MMA helpers
// ---------------------------------------------------------------------------
__device__ __forceinline__ void ldsm4(unsigned* r, unsigned addr) {
    asm volatile("ldmatrix.sync.aligned.m8n8.x4.shared.b16 {%0,%1,%2,%3}, [%4];"
                 : "=r"(r[0]), "=r"(r[1]), "=r"(r[2]), "=r"(r[3]) : "r"(addr));
}
__device__ __forceinline__ void ldsm4t(unsigned* r, unsigned addr) {
    asm volatile("ldmatrix.sync.aligned.m8n8.x4.trans.shared.b16 {%0,%1,%2,%3}, [%4];"
                 : "=r"(r[0]), "=r"(r[1]), "=r"(r[2]), "=r"(r[3]) : "r"(addr));
}
__device__ __forceinline__ void mma16816(float* d, const unsigned* a, unsigned b0, unsigned b1) {
    asm volatile("mma.sync.aligned.m16n8k16.row.col.f32.bf16.bf16.f32 "
                 "{%0,%1,%2,%3}, {%4,%5,%6,%7}, {%8,%9}, {%0,%1,%2,%3};"
                 : "+f"(d[0]), "+f"(d[1]), "+f"(d[2]), "+f"(d[3])
                 : "r"(a[0]), "r"(a[1]), "r"(a[2]), "r"(a[3]), "r"(b0), "r"(b1));
}

// ---------------------------------------------------------------------------
// Kernel 2: approx gate scores via bf16 tensor-core GEMM, 2 rows i per block.
// grid=512, 256 threads (8 warps as 4m x 2n, two i's processed per hc chunk).
// ---------------------------------------------------------------------------
#define SJ 136   // padded bf16 stride for s tile (row = 272B)
#define CH 72    // padded bf16 stride for c tile (row = 144B)
#define OFS_C    69632            // c tiles: 2 x 18432
#define OFS_SC   106496           // score_sm: 2 x 256 f32
#define OFS_UB   108544           // ub_sm:    2 x 256 f32
#define OFS_W2   110592           // w2_sm:    256 f32
#define OFS_SI   111616           // si_sm:    2 x 128 f32
#define GSC_SMEM 112640

__global__ __launch_bounds__(256, 2) void gscore_mma_kernel(
    const float* __restrict__ s,
    const float* __restrict__ W1,
    const float* __restrict__ b1,
    const float* __restrict__ W2,
    const float* __restrict__ b2,
    float* __restrict__ scores)
{
    extern __shared__ unsigned char dynsm[];
    __nv_bfloat16* s_sm = (__nv_bfloat16*)dynsm;
    __nv_bfloat16* c_sm = (__nv_bfloat16*)(dynsm + OFS_C);     // [2][128][CH]
    float* score_sm = (float*)(dynsm + OFS_SC);                // [2][256]
    float* ub_sm    = (float*)(dynsm + OFS_UB);                // [2][256]
    float* w2_sm    = (float*)(dynsm + OFS_W2);
    float* si_sm    = (float*)(dynsm + OFS_SI);                // [2][128]

    int bi0 = blockIdx.x * 2;       // first of two rows; same batch b
    int b   = bi0 >> 8;
    int tid = threadIdx.x;
    int lane = tid & 31;
    int warp = tid >> 5;

    score_sm[tid]       = 0.f;
    score_sm[256 + tid] = 0.f;
    float b1v = b1[tid];
    ub_sm[tid]       = Ug_buf[bi0 * Hv + tid] + b1v;
    ub_sm[256 + tid] = Ug_buf[(bi0 + 1) * Hv + tid] + b1v;
    w2_sm[tid] = W2[tid];
    {
        int r = tid >> 7, d = tid & 127;
        si_sm[r * 128 + d] = s[(bi0 + r) * Dv + d];
    }

    // copy s_b (bf16) into padded smem, 16B chunks
    {
        const uint4* src = (const uint4*)(s_bf16_buf + b * Nv * Dv);
#pragma unroll
        for (int k = 0; k < 16; k++) {
            int t = k * 256 + tid;            // 0..4095
            int row = t >> 4;
            int c8  = t & 15;
            *(uint4*)((char*)s_sm + row * 272 + c8 * 16) = src[t];
        }
    }
    __syncthreads();

    const unsigned sbase = (unsigned)__cvta_generic_to_shared(s_sm);
    const unsigned cbase = (unsigned)__cvta_generic_to_shared(c_sm);
    int wm = (warp & 3) * 64;
    int wn = (warp >> 2) * 32;
    int aRow = wm + (lane & 15);
    int aColB = ((lane >> 4) << 3) * 2;       // bytes
    int bK   = lane & 15;
    int bH   = wn + ((lane >> 4) << 3);

    for (int hc = 0; hc < 4; hc++) {
        // build c chunks for both i's (shared W loads)
#pragma unroll
        for (int k = 0; k < 32; k++) {
            int t = k * 256 + tid;            // 0..8191
            int d = t >> 6;
            int h = t & 63;
            int H = hc * 64 + h;
            float wmv = W1[(Dv + d) * Hv + H];
            float wbv = W1[(2 * Dv + d) * Hv + H];
            c_sm[d * CH + h]        = __float2bfloat16(fmaf(si_sm[d], wbv, wmv));
            c_sm[9216 + d * CH + h] = __float2bfloat16(fmaf(si_sm[128 + d], wbv, wmv));
        }
        __syncthreads();

#pragma unroll 1
        for (int ii = 0; ii < 2; ii++) {
            float acc[16][4];
#pragma unroll
            for (int q = 0; q < 16; q++) { acc[q][0]=0.f; acc[q][1]=0.f; acc[q][2]=0.f; acc[q][3]=0.f; }

            unsigned cb = cbase + (unsigned)(ii * 18432);
#pragma unroll
            for (int ks = 0; ks < 8; ks++) {
                unsigned a[4][4], bq[2][4];
#pragma unroll
                for (int mt = 0; mt < 4; mt++) {
                    unsigned addr = sbase + (unsigned)((aRow + mt * 16) * (SJ * 2) + ks * 32) + aColB;
                    ldsm4(a[mt], addr);
                }
#pragma unroll
                for (int nt = 0; nt < 2; nt++) {
                    unsigned addr = cb + (unsigned)((ks * 16 + bK) * (CH * 2) + (bH + nt * 16) * 2);
                    ldsm4t(bq[nt], addr);
                }
#pragma unroll
                for (int mt = 0; mt < 4; mt++)
#pragma unroll
                    for (int n8 = 0; n8 < 4; n8++)
                        mma16816(acc[mt * 4 + n8], a[mt], bq[n8 >> 1][(n8 & 1) * 2], bq[n8 >> 1][(n8 & 1) * 2 + 1]);
            }

            // epilogue: relu + dot W2, quad reduce, accumulate into score_sm[ii]
            int rr = wm + (lane >> 2);
            int hb = hc * 64 + wn + (lane & 3) * 2;
            float* ssm = score_sm + ii * 256;
            const float* ubp = ub_sm + ii * 256;
#pragma unroll
            for (int mt = 0; mt < 4; mt++) {
                float p0 = 0.f, p1 = 0.f;
#pragma unroll
                for (int n8 = 0; n8 < 4; n8++) {
                    int h0 = hb + n8 * 8;
                    float u0 = ubp[h0], u1 = ubp[h0 + 1];
                    float w0 = w2_sm[h0], w1 = w2_sm[h0 + 1];
                    const float* A = acc[mt * 4 + n8];
                    p0 = fmaf(fmaxf(A[0] + u0, 0.f), w0, p0);
                    p0 = fmaf(fmaxf(A[1] + u1, 0.f), w1, p0);
                    p1 = fmaf(fmaxf(A[2] + u0, 0.f), w0, p1);
                    p1 = fmaf(fmaxf(A[3] + u1, 0.f), w1, p1);
                }
                p0 += __shfl_xor_sync(0xffffffffu, p0, 1);
                p0 += __shfl_xor_sync(0xffffffffu, p0, 2);
                p1 += __shfl_xor_sync(0xffffffffu, p1, 1);
                p1 += __shfl_xor_sync(0xffffffffu, p1, 2);
                if ((lane & 3) == 0) {
                    atomicAdd(&ssm[rr + mt * 16], p0);
                    atomicAdd(&ssm[rr + mt * 16 + 8], p1);
                }
            }
        }
        __syncthreads();
    }
    float b2v = b2[0];
    scores[bi0 * Nv + tid]       = score_sm[tid] + b2v;
    scores[(bi0 + 1) * Nv + tid] = score_sm[256 + tid] + b2v;
}

// ---------------------------------------------------------------------------
// Kernel 3: approx top-12 -> fused exact fp32 rescore (gate + att, FFMA2)
// -> exact top-8 -> softmax -> outputs. grid = 512 blocks (2 rows), 256 thr.
// Also zeroes this block's gate/att rows (zero_kernel folded in).
// ---------------------------------------------------------------------------
#define TPAD 28   // selT row stride in floats (2*Cv=24 -> pad 28, 16B aligned)

__global__ __launch_bounds__(256) void topk_att_kernel(
    const float* __restrict__ s,
    const float* __restrict__ Wg1,
    const float* __restrict__ bg1,
    const float* __restrict__ Wg2,
    const float* __restrict__ bg2,
    const float* __restrict__ Wa1,
    const float* __restrict__ ba1,
    const float* __restrict__ Wa2,
    const float* __restrict__ ba2,
    float* __restrict__ ctx,
    float* __restrict__ gate,
    float* __restrict__ att)
{
    int b  = blockIdx.x >> 7;
    int i0 = (blockIdx.x & 127) << 1;
    int tid = threadIdx.x;
    int lane = tid & 31;
    int warp = tid >> 5;

    __shared__ float sc[2][Nv];
    __shared__ float selT[Dv][TPAD];             // d-major candidate tile
    __shared__ unsigned long long sip[Dv];       // packed (si_r0[d], si_r1[d])
    __shared__ float ug2[2][Hv];
    __shared__ float ua2[2][Hv];
    __shared__ float bg1s[Hv], wg2s[Hv], ba1s[Hv], wa2s[Hv];
    __shared__ float partg[2][Cv][8];
    __shared__ float parta[2][Cv][8];
    __shared__ float exacts[2][Cv];
    __shared__ float alog[2][Cv];
    __shared__ int   sel[2][Cv];
    __shared__ int   fsel[2][Kv];
    __shared__ int   fj[2][Kv];
    __shared__ float logit[2][Kv];
    __shared__ float attw[2][Kv];

    // zero this block's gate + att rows (2 rows x 256 each)
    {
        float4 z = make_float4(0.f, 0.f, 0.f, 0.f);
        float4* gp = (float4*)(gate + (b * Nv + i0) * Nv);
        float4* ap = (float4*)(att  + (b * Nv + i0) * Nv);
        if (tid < 128) { gp[tid] = z; ap[tid] = z; }
    }

#pragma unroll
    for (int r = 0; r < 2; r++) {
        sc[r][tid]  = g_scores_buf[(b * Nv + i0 + r) * Nv + tid];
        ug2[r][tid] = Ug_buf[(b * Nv + i0 + r) * Hv + tid];
        ua2[r][tid] = Ua_buf[(b * Nv + i0 + r) * Hv + tid];
    }
    bg1s[tid] = bg1[tid];
    wg2s[tid] = Wg2[tid];
    ba1s[tid] = ba1[tid];
    wa2s[tid] = Wa2[tid];
    if (tid < Dv) {
        sip[tid] = pack2(s[(b * Nv + i0) * Dv + tid],
                         s[(b * Nv + i0 + 1) * Dv + tid]);
    }
    __syncthreads();

    // approx top-12 per row (warps 0,1)
    if (warp < 2) {
        int r = warp;
        for (int t = 0; t < Cv; t++) {
            float bv = -INFINITY; int bidx = Nv;
#pragma unroll
            for (int k = 0; k < 8; k++) {
                int q = k * 32 + lane;
                float v = sc[r][q];
                if (v > bv || (v == bv && q < bidx)) { bv = v; bidx = q; }
            }
#pragma unroll
            for (int off = 16; off > 0; off >>= 1) {
                float ov = __shfl_down_sync(0xffffffffu, bv, off);
                int   oi = __shfl_down_sync(0xffffffffu, bidx, off);
                if (ov > bv || (ov == bv && oi < bidx)) { bv = ov; bidx = oi; }
            }
            bidx = __shfl_sync(0xffffffffu, bidx, 0);
            if (lane == 0) { sel[r][t] = bidx; sc[r][bidx] = -INFINITY; }
            __syncwarp();
        }
    }
    __syncthreads();

    // gather candidate s_j rows, transposed: selT[d][r*Cv + c]
    // 2*12*128 = 3072 elems, 12 iters
#pragma unroll
    for (int k = 0; k < 12; k++) {
        int ii = k * 256 + tid;           // 0..3071
        int d  = ii & 127;
        int rc = ii >> 7;                 // 0..23
        int r  = (rc >= Cv) ? 1 : 0;
        int c  = rc - r * Cv;
        selT[d][rc] = s[(b * Nv + sel[r][c]) * Dv + d];
    }
    __syncthreads();

    // fused exact fp32 rescore: gate + att hidden units for all 24 candidates.
    // thread owns hidden index h = tid; FFMA2 packs candidate pairs.
    int h = tid;
    unsigned long long ag[2][6], aa[2][6];
#pragma unroll
    for (int r = 0; r < 2; r++)
#pragma unroll
        for (int q = 0; q < 6; q++) { ag[r][q] = 0ull; aa[r][q] = 0ull; }

    const float* pgm = Wg1 + Dv * Hv + h;
    const float* pgb = Wg1 + 2 * Dv * Hv + h;
    const float* pam = Wa1 + Dv * Hv + h;
    const float* pab = Wa1 + 2 * Dv * Hv + h;

#pragma unroll 2
    for (int d = 0; d < Dv; d++) {
        float wgm = pgm[d * Hv];
        float wgb = pgb[d * Hv];
        float wam = pam[d * Hv];
        float wab = pab[d * Hv];
        float2 si = unpack2(sip[d]);
        unsigned long long cg0 = pack2(fmaf(si.x, wgb, wgm), fmaf(si.x, wgb, wgm));
        unsigned long long cg1 = pack2(fmaf(si.y, wgb, wgm), fmaf(si.y, wgb, wgm));
        unsigned long long ca0 = pack2(fmaf(si.x, wab, wam), fmaf(si.x, wab, wam));
        unsigned long long ca1 = pack2(fmaf(si.y, wab, wam), fmaf(si.y, wab, wam));

        const ulonglong2* rowp = (const ulonglong2*)&selT[d][0];
#pragma unroll
        for (int q = 0; q < 3; q++) {
            ulonglong2 v0 = rowp[q];          // r0 candidates 4q..4q+3
            ffma2(ag[0][q * 2],     v0.x, cg0);
            ffma2(ag[0][q * 2 + 1], v0.y, cg0);
            ffma2(aa[0][q * 2],     v0.x, ca0);
            ffma2(aa[0][q * 2 + 1], v0.y, ca0);
            ulonglong2 v1 = rowp[3 + q];      // r1 candidates
            ffma2(ag[1][q * 2],     v1.x, cg1);
            ffma2(ag[1][q * 2 + 1], v1.y, cg1);
            ffma2(aa[1][q * 2],     v1.x, ca1);
            ffma2(aa[1][q * 2 + 1], v1.y, ca1);
        }
    }

    // relu + dot W2 for both MLPs, warp reduce, stash partials
#pragma unroll
    for (int r = 0; r < 2; r++) {
        float ug = ug2[r][h] + bg1s[h];
        float ua = ua2[r][h] + ba1s[h];
        float wg = wg2s[h];
        float wa = wa2s[h];
#pragma unroll
        for (int q = 0; q < 6; q++) {
            float2 g2 = unpack2(ag[r][q]);
            float2 a2 = unpack2(aa[r][q]);
#pragma unroll
            for (int half = 0; half < 2; half++) {
                int t = q * 2 + half;
                float gv = half ? g2.y : g2.x;
                float av = half ? a2.y : a2.x;
                float vg = fmaxf(gv + ug, 0.f) * wg;
                float va = fmaxf(av + ua, 0.f) * wa;
#pragma unroll
                for (int off = 16; off > 0; off >>= 1) {
                    vg += __shfl_xor_sync(0xffffffffu, vg, off);
                    va += __shfl_xor_sync(0xffffffffu, va, off);
                }
                if (lane == 0) { partg[r][t][warp] = vg; parta[r][t][warp] = va; }
            }
        }
    }
    __syncthreads();

    // block sums
    if (tid < 2 * Cv) {
        int r = tid / Cv, t = tid % Cv;
        float sSum = 0.f;
#pragma unroll
        for (int w8 = 0; w8 < 8; w8++) sSum += partg[r][t][w8];
        exacts[r][t] = sSum + bg2[0];
    } else if (tid >= 64 && tid < 64 + 2 * Cv) {
        int k = tid - 64;
        int r = k / Cv, t = k % Cv;
        float sSum = 0.f;
#pragma unroll
        for (int w8 = 0; w8 < 8; w8++) sSum += parta[r][t][w8];
        alog[r][t] = sSum + ba2[0];
    }
    __syncthreads();

    // exact top-8 among 12 candidates (tie -> lowest original j)
    if (warp < 2) {
        int r = warp;
        float v = (lane < Cv) ? exacts[r][lane] : -INFINITY;
        int jj  = (lane < Cv) ? sel[r][lane] : (1 << 30);
        int cc  = lane;
        for (int t = 0; t < Kv; t++) {
            float bv = v; int bj = jj; int bc = cc;
#pragma unroll
            for (int off = 16; off > 0; off >>= 1) {
                float ov = __shfl_down_sync(0xffffffffu, bv, off);
                int   oj = __shfl_down_sync(0xffffffffu, bj, off);
                int   oc = __shfl_down_sync(0xffffffffu, bc, off);
                if (ov > bv || (ov == bv && oj < bj)) { bv = ov; bj = oj; bc = oc; }
            }
            bc = __shfl_sync(0xffffffffu, bc, 0);
            bj = __shfl_sync(0xffffffffu, bj, 0);
            if (lane == 0) { fsel[r][t] = bc; fj[r][t] = bj; }
            if (cc == bc) v = -INFINITY;
        }
    }
    __syncthreads();

    if (tid < 16) {
        int r = tid >> 3, t = tid & 7;
        logit[r][t] = alog[r][fsel[r][t]];
    }
    __syncthreads();
    if (tid < 2) {
        float m = -INFINITY;
#pragma unroll
        for (int t = 0; t < Kv; t++) m = fmaxf(m, logit[tid][t]);
        float e[Kv], ssum = 0.f;
#pragma unroll
        for (int t = 0; t < Kv; t++) { e[t] = expf(logit[tid][t] - m); ssum += e[t]; }
#pragma unroll
        for (int t = 0; t < Kv; t++) attw[tid][t] = e[t] / ssum;
    }
    __syncthreads();

    if (tid < 16) {
        int r = tid >> 3, t = tid & 7;
        int i = i0 + r, js = fj[r][t];
        gate[(b * Nv + i) * Nv + js] = 1.0f;
        att [(b * Nv + i) * Nv + js] = attw[r][t];
    }
    if (tid < Dv) {
        int d = tid;
#pragma unroll
        for (int r = 0; r < 2; r++) {
            float cv = 0.f;
#pragma unroll
            for (int t = 0; t < Kv; t++)
                cv = fmaf(attw[r][t], selT[d][r * Cv + fsel[r][t]], cv);
            ctx[(b * Nv + i0 + r) * Dv + d] = cv;
        }
    }
}

// ---------------------------------------------------------------------------
extern "C" void kernel_launch(void* const* d_in, const int* in_sizes, int n_in,
                              void* d_out, int out_size)
{
    const float* s   = (const float*)d_in[0];
    const float* Wg1 = (const float*)d_in[1];
    const float* bg1 = (const float*)d_in[2];
    const float* Wg2 = (const float*)d_in[3];
    const float* bg2 = (const float*)d_in[4];
    const float* Wa1 = (const float*)d_in[5];
    const float* ba1 = (const float*)d_in[6];
    const float* Wa2 = (const float*)d_in[7];
    const float* ba2 = (const float*)d_in[8];

    float* out  = (float*)d_out;
    float* ctx  = out;
    float* gate = out + Bv * Nv * Dv;
    float* att  = gate + Bv * Nv * Nv;

    float* g_scores; cudaGetSymbolAddress((void**)&g_scores, g_scores_buf);

    cudaFuncSetAttribute(gscore_mma_kernel,
                         cudaFuncAttributeMaxDynamicSharedMemorySize, GSC_SMEM);

    u_kernel<<<ROWS / 8, 256>>>(s, Wg1, Wa1);
    gscore_mma_kernel<<<ROWS / 2, 256, GSC_SMEM>>>(s, Wg1, bg1, Wg2, bg2, g_scores);
    topk_att_kernel<<<ROWS / 2, 256>>>(s, Wg1, bg1, Wg2, bg2,
                                       Wa1, ba1, Wa2, ba2, ctx, gate, att);
}

// round 5
// speedup vs baseline: 3.8453x; 1.0217x over previous
#include <cuda_runtime.h>
#include <cuda_bf16.h>
#include <math.h>

// Problem constants
#define Bv 4
#define Nv 256
#define Dv 128
#define Hv 256
#define Kv 8
#define Cv 12               // candidate count for exact rescore
#define ROWS (Bv * Nv)      // 1024

// ---------------------------------------------------------------------------
// f32x2 packed helpers (sm_103a dual fp32 pipe)
// ---------------------------------------------------------------------------
__device__ __forceinline__ void ffma2(unsigned long long& d,
                                      unsigned long long a,
                                      unsigned long long b) {
    asm("fma.rn.f32x2 %0, %1, %2, %0;" : "+l"(d) : "l"(a), "l"(b));
}
__device__ __forceinline__ unsigned long long pack2(float x, float y) {
    unsigned long long r;
    asm("mov.b64 %0, {%1, %2};" : "=l"(r) : "f"(x), "f"(y));
    return r;
}
__device__ __forceinline__ float2 unpack2(unsigned long long v) {
    float2 r;
    asm("mov.b64 {%0, %1}, %2;" : "=f"(r.x), "=f"(r.y) : "l"(v));
    return r;
}

// ---------------------------------------------------------------------------
// MMA helpers
// ---------------------------------------------------------------------------
__device__ __forceinline__ void ldsm4(unsigned* r, unsigned addr) {
    asm volatile("ldmatrix.sync.aligned.m8n8.x4.shared.b16 {%0,%1,%2,%3}, [%4];"
                 : "=r"(r[0]), "=r"(r[1]), "=r"(r[2]), "=r"(r[3]) : "r"(addr));
}
__device__ __forceinline__ void ldsm4t(unsigned* r, unsigned addr) {
    asm volatile("ldmatrix.sync.aligned.m8n8.x4.trans.shared.b16 {%0,%1,%2,%3}, [%4];"
                 : "=r"(r[0]), "=r"(r[1]), "=r"(r[2]), "=r"(r[3]) : "r"(addr));
}
__device__ __forceinline__ void mma16816(float* d, const unsigned* a, unsigned b0, unsigned b1) {
    asm volatile("mma.sync.aligned.m16n8k16.row.col.f32.bf16.bf16.f32 "
                 "{%0,%1,%2,%3}, {%4,%5,%6,%7}, {%8,%9}, {%0,%1,%2,%3};"
                 : "+f"(d[0]), "+f"(d[1]), "+f"(d[2]), "+f"(d[3])
                 : "r"(a[0]), "r"(a[1]), "r"(a[2]), "r"(a[3]), "r"(b0), "r"(b1));
}

// ---------------------------------------------------------------------------
// Fused kernel: per block (2 rows i0,i0+1 of batch b):
//   inline U (both MLPs) + s->bf16 smem, bf16 MMA gate scores,
//   approx top-12, exact FFMA2 rescore (gate+att), exact top-8,
//   softmax, outputs. grid = 512, 256 threads.
// ---------------------------------------------------------------------------
#define SJ 136   // padded bf16 stride for s tile (row = 272B)
#define CH 72    // padded bf16 stride for c tile (row = 144B)
#define TPAD 28  // selT row stride in floats

#define OFS_C     69632           // c tile 18432 (aliased by selT post-GEMM)
#define OFS_SCORE 88064           // 2 x 256 f32
#define OFS_UB    90112           // 2 x 256 f32 (Ug + bg1)
#define OFS_UAB   92160           // 2 x 256 f32 (Ua + ba1)
#define OFS_W2    94208           // 256 f32
#define OFS_WA2   95232           // 256 f32
#define OFS_SI    96256           // 2 x 128 f32
#define FUS_SMEM  97280

__global__ __launch_bounds__(256, 2) void fused_kernel(
    const float* __restrict__ s,
    const float* __restrict__ Wg1,
    const float* __restrict__ bg1,
    const float* __restrict__ Wg2,
    const float* __restrict__ bg2,
    const float* __restrict__ Wa1,
    const float* __restrict__ ba1,
    const float* __restrict__ Wa2,
    const float* __restrict__ ba2,
    float* __restrict__ ctx,
    float* __restrict__ gate,
    float* __restrict__ att)
{
    extern __shared__ unsigned char dynsm[];
    __nv_bfloat16* s_sm = (__nv_bfloat16*)dynsm;
    __nv_bfloat16* c_sm = (__nv_bfloat16*)(dynsm + OFS_C);
    float (*selT)[TPAD] = (float (*)[TPAD])(dynsm + OFS_C);    // alias, post-GEMM
    float* score_sm = (float*)(dynsm + OFS_SCORE);             // [2][256]
    float* ub_sm    = (float*)(dynsm + OFS_UB);                // [2][256] Ug+bg1
    float* uab_sm   = (float*)(dynsm + OFS_UAB);               // [2][256] Ua+ba1
    float* w2_sm    = (float*)(dynsm + OFS_W2);
    float* wa2_sm   = (float*)(dynsm + OFS_WA2);
    float* si_sm    = (float*)(dynsm + OFS_SI);                // [2][128]

    __shared__ float partg[2][Cv][8];
    __shared__ float parta[2][Cv][8];
    __shared__ float exacts[2][Cv];
    __shared__ float alog[2][Cv];
    __shared__ int   sel[2][Cv];
    __shared__ int   fsel[2][Kv];
    __shared__ int   fj[2][Kv];
    __shared__ float logit[2][Kv];
    __shared__ float attw[2][Kv];

    int bi0 = blockIdx.x * 2;       // global row index (b*Nv + i0)
    int b   = bi0 >> 8;
    int i0  = bi0 & 255;
    int tid = threadIdx.x;
    int lane = tid & 31;
    int warp = tid >> 5;

    // zero this block's gate + att rows (2 rows x 256 each)
    {
        float4 z = make_float4(0.f, 0.f, 0.f, 0.f);
        float4* gp = (float4*)(gate + bi0 * Nv);
        float4* ap = (float4*)(att  + bi0 * Nv);
        if (tid < 128) { gp[tid] = z; ap[tid] = z; }
    }

    // si + small vectors
    {
        int r = tid >> 7, d = tid & 127;
        si_sm[r * 128 + d] = s[(bi0 + r) * Dv + d];
    }
    w2_sm[tid]  = Wg2[tid];
    wa2_sm[tid] = Wa2[tid];
    score_sm[tid]       = 0.f;
    score_sm[256 + tid] = 0.f;
    __syncthreads();

    // s_b -> bf16 padded smem (float4 loads, 8B stores)
    {
        const float4* sp4 = (const float4*)(s + b * Nv * Dv);
#pragma unroll
        for (int k = 0; k < 32; k++) {
            int t = k * 256 + tid;            // 0..8191 float4s
            int row = t >> 5;
            int c4  = t & 31;
            float4 v = sp4[t];
            __nv_bfloat162 lo = __floats2bfloat162_rn(v.x, v.y);
            __nv_bfloat162 hi = __floats2bfloat162_rn(v.z, v.w);
            uint2 pk;
            pk.x = *(unsigned*)&lo;
            pk.y = *(unsigned*)&hi;
            *(uint2*)((char*)s_sm + row * 272 + c4 * 8) = pk;
        }
    }

    // inline U for both MLPs, both rows (thread owns h = tid); fold biases in
    {
        int h = tid;
        float ug0 = bg1[h], ug1 = ug0;
        float ua0 = ba1[h], ua1 = ua0;
#pragma unroll 8
        for (int d = 0; d < Dv; d++) {
            float wg = Wg1[d * Hv + h];
            float wa = Wa1[d * Hv + h];
            float s0 = si_sm[d];
            float s1 = si_sm[128 + d];
            ug0 = fmaf(s0, wg, ug0);
            ug1 = fmaf(s1, wg, ug1);
            ua0 = fmaf(s0, wa, ua0);
            ua1 = fmaf(s1, wa, ua1);
        }
        ub_sm[h]        = ug0;
        ub_sm[256 + h]  = ug1;
        uab_sm[h]       = ua0;
        uab_sm[256 + h] = ua1;
    }
    __syncthreads();

    // ---------------- GEMM phase ----------------
    const unsigned sbase = (unsigned)__cvta_generic_to_shared(s_sm);
    const unsigned cbase = (unsigned)__cvta_generic_to_shared(c_sm);
    int wm = (warp & 3) * 64;
    int wn = (warp >> 2) * 32;
    int aRow = wm + (lane & 15);
    int aColB = ((lane >> 4) << 3) * 2;       // bytes
    int bK   = lane & 15;
    int bH   = wn + ((lane >> 4) << 3);

#pragma unroll 1
    for (int ii = 0; ii < 2; ii++) {
#pragma unroll 1
        for (int hc = 0; hc < 4; hc++) {
            // build c chunk [128][64] bf16 for row ii
#pragma unroll
            for (int k = 0; k < 32; k++) {
                int t = k * 256 + tid;            // 0..8191
                int d = t >> 6;
                int h = t & 63;
                int H = hc * 64 + h;
                float wmv = Wg1[(Dv + d) * Hv + H];
                float wbv = Wg1[(2 * Dv + d) * Hv + H];
                c_sm[d * CH + h] = __float2bfloat16(fmaf(si_sm[ii * 128 + d], wbv, wmv));
            }
            __syncthreads();

            float acc[16][4];
#pragma unroll
            for (int q = 0; q < 16; q++) { acc[q][0]=0.f; acc[q][1]=0.f; acc[q][2]=0.f; acc[q][3]=0.f; }

#pragma unroll
            for (int ks = 0; ks < 8; ks++) {
                unsigned a[4][4], bq[2][4];
#pragma unroll
                for (int mt = 0; mt < 4; mt++) {
                    unsigned addr = sbase + (unsigned)((aRow + mt * 16) * (SJ * 2) + ks * 32) + aColB;
                    ldsm4(a[mt], addr);
                }
#pragma unroll
                for (int nt = 0; nt < 2; nt++) {
                    unsigned addr = cbase + (unsigned)((ks * 16 + bK) * (CH * 2) + (bH + nt * 16) * 2);
                    ldsm4t(bq[nt], addr);
                }
#pragma unroll
                for (int mt = 0; mt < 4; mt++)
#pragma unroll
                    for (int n8 = 0; n8 < 4; n8++)
                        mma16816(acc[mt * 4 + n8], a[mt], bq[n8 >> 1][(n8 & 1) * 2], bq[n8 >> 1][(n8 & 1) * 2 + 1]);
            }

            // epilogue: relu + dot W2, quad reduce, accumulate
            int rr = wm + (lane >> 2);
            int hb = hc * 64 + wn + (lane & 3) * 2;
            float* ssm = score_sm + ii * 256;
            const float* ubp = ub_sm + ii * 256;
#pragma unroll
            for (int mt = 0; mt < 4; mt++) {
                float p0 = 0.f, p1 = 0.f;
#pragma unroll
                for (int n8 = 0; n8 < 4; n8++) {
                    int h0 = hb + n8 * 8;
                    float u0 = ubp[h0], u1 = ubp[h0 + 1];
                    float w0 = w2_sm[h0], w1 = w2_sm[h0 + 1];
                    const float* A = acc[mt * 4 + n8];
                    p0 = fmaf(fmaxf(A[0] + u0, 0.f), w0, p0);
                    p0 = fmaf(fmaxf(A[1] + u1, 0.f), w1, p0);
                    p1 = fmaf(fmaxf(A[2] + u0, 0.f), w0, p1);
                    p1 = fmaf(fmaxf(A[3] + u1, 0.f), w1, p1);
                }
                p0 += __shfl_xor_sync(0xffffffffu, p0, 1);
                p0 += __shfl_xor_sync(0xffffffffu, p0, 2);
                p1 += __shfl_xor_sync(0xffffffffu, p1, 1);
                p1 += __shfl_xor_sync(0xffffffffu, p1, 2);
                if ((lane & 3) == 0) {
                    atomicAdd(&ssm[rr + mt * 16], p0);
                    atomicAdd(&ssm[rr + mt * 16 + 8], p1);
                }
            }
            __syncthreads();
        }
    }

    // ---------------- selection + rescore phase ----------------
    // approx top-12 per row directly on score_sm (destructive)
    if (warp < 2) {
        int r = warp;
        float* scr = score_sm + r * 256;
        for (int t = 0; t < Cv; t++) {
            float bv = -INFINITY; int bidx = Nv;
#pragma unroll
            for (int k = 0; k < 8; k++) {
                int q = k * 32 + lane;
                float v = scr[q];
                if (v > bv || (v == bv && q < bidx)) { bv = v; bidx = q; }
            }
#pragma unroll
            for (int off = 16; off > 0; off >>= 1) {
                float ov = __shfl_down_sync(0xffffffffu, bv, off);
                int   oi = __shfl_down_sync(0xffffffffu, bidx, off);
                if (ov > bv || (ov == bv && oi < bidx)) { bv = ov; bidx = oi; }
            }
            bidx = __shfl_sync(0xffffffffu, bidx, 0);
            if (lane == 0) { sel[r][t] = bidx; scr[bidx] = -INFINITY; }
            __syncwarp();
        }
    }
    __syncthreads();

    // gather candidate s_j rows (fp32, from global, L2-hot) into selT (aliases c_sm)
#pragma unroll
    for (int k = 0; k < 12; k++) {
        int ii = k * 256 + tid;           // 0..3071
        int d  = ii & 127;
        int rc = ii >> 7;                 // 0..23
        int r  = (rc >= Cv) ? 1 : 0;
        int c  = rc - r * Cv;
        selT[d][rc] = s[(b * Nv + sel[r][c]) * Dv + d];
    }
    __syncthreads();

    // fused exact fp32 rescore (gate + att) for all 24 candidates, FFMA2
    int h = tid;
    unsigned long long ag[2][6], aa[2][6];
#pragma unroll
    for (int r = 0; r < 2; r++)
#pragma unroll
        for (int q = 0; q < 6; q++) { ag[r][q] = 0ull; aa[r][q] = 0ull; }

    const float* pgm = Wg1 + Dv * Hv + h;
    const float* pgb = Wg1 + 2 * Dv * Hv + h;
    const float* pam = Wa1 + Dv * Hv + h;
    const float* pab = Wa1 + 2 * Dv * Hv + h;

#pragma unroll 2
    for (int d = 0; d < Dv; d++) {
        float wgm = pgm[d * Hv];
        float wgb = pgb[d * Hv];
        float wam = pam[d * Hv];
        float wab = pab[d * Hv];
        float s0 = si_sm[d], s1 = si_sm[128 + d];
        float cg0s = fmaf(s0, wgb, wgm);
        float cg1s = fmaf(s1, wgb, wgm);
        float ca0s = fmaf(s0, wab, wam);
        float ca1s = fmaf(s1, wab, wam);
        unsigned long long cg0 = pack2(cg0s, cg0s);
        unsigned long long cg1 = pack2(cg1s, cg1s);
        unsigned long long ca0 = pack2(ca0s, ca0s);
        unsigned long long ca1 = pack2(ca1s, ca1s);

        const ulonglong2* rowp = (const ulonglong2*)&selT[d][0];
#pragma unroll
        for (int q = 0; q < 3; q++) {
            ulonglong2 v0 = rowp[q];          // r0 candidates 4q..4q+3
            ffma2(ag[0][q * 2],     v0.x, cg0);
            ffma2(ag[0][q * 2 + 1], v0.y, cg0);
            ffma2(aa[0][q * 2],     v0.x, ca0);
            ffma2(aa[0][q * 2 + 1], v0.y, ca0);
            ulonglong2 v1 = rowp[3 + q];      // r1 candidates
            ffma2(ag[1][q * 2],     v1.x, cg1);
            ffma2(ag[1][q * 2 + 1], v1.y, cg1);
            ffma2(aa[1][q * 2],     v1.x, ca1);
            ffma2(aa[1][q * 2 + 1], v1.y, ca1);
        }
    }

    // relu + dot W2 for both MLPs, warp reduce, stash partials
#pragma unroll
    for (int r = 0; r < 2; r++) {
        float ug = ub_sm[r * 256 + h];     // already includes bg1
        float ua = uab_sm[r * 256 + h];    // already includes ba1
        float wg = w2_sm[h];
        float wa = wa2_sm[h];
#pragma unroll
        for (int q = 0; q < 6; q++) {
            float2 g2 = unpack2(ag[r][q]);
            float2 a2 = unpack2(aa[r][q]);
#pragma unroll
            for (int half = 0; half < 2; half++) {
                int t = q * 2 + half;
                float gv = half ? g2.y : g2.x;
                float av = half ? a2.y : a2.x;
                float vg = fmaxf(gv + ug, 0.f) * wg;
                float va = fmaxf(av + ua, 0.f) * wa;
#pragma unroll
                for (int off = 16; off > 0; off >>= 1) {
                    vg += __shfl_xor_sync(0xffffffffu, vg, off);
                    va += __shfl_xor_sync(0xffffffffu, va, off);
                }
                if (lane == 0) { partg[r][t][warp] = vg; parta[r][t][warp] = va; }
            }
        }
    }
    __syncthreads();

    // block sums
    if (tid < 2 * Cv) {
        int r = tid / Cv, t = tid % Cv;
        float sSum = 0.f;
#pragma unroll
        for (int w8 = 0; w8 < 8; w8++) sSum += partg[r][t][w8];
        exacts[r][t] = sSum + bg2[0];
    } else if (tid >= 64 && tid < 64 + 2 * Cv) {
        int k = tid - 64;
        int r = k / Cv, t = k % Cv;
        float sSum = 0.f;
#pragma unroll
        for (int w8 = 0; w8 < 8; w8++) sSum += parta[r][t][w8];
        alog[r][t] = sSum + ba2[0];
    }
    __syncthreads();

    // exact top-8 among 12 candidates (tie -> lowest original j)
    if (warp < 2) {
        int r = warp;
        float v = (lane < Cv) ? exacts[r][lane] : -INFINITY;
        int jj  = (lane < Cv) ? sel[r][lane] : (1 << 30);
        int cc  = lane;
        for (int t = 0; t < Kv; t++) {
            float bv = v; int bj = jj; int bc = cc;
#pragma unroll
            for (int off = 16; off > 0; off >>= 1) {
                float ov = __shfl_down_sync(0xffffffffu, bv, off);
                int   oj = __shfl_down_sync(0xffffffffu, bj, off);
                int   oc = __shfl_down_sync(0xffffffffu, bc, off);
                if (ov > bv || (ov == bv && oj < bj)) { bv = ov; bj = oj; bc = oc; }
            }
            bc = __shfl_sync(0xffffffffu, bc, 0);
            bj = __shfl_sync(0xffffffffu, bj, 0);
            if (lane == 0) { fsel[r][t] = bc; fj[r][t] = bj; }
            if (cc == bc) v = -INFINITY;
        }
    }
    __syncthreads();

    if (tid < 16) {
        int r = tid >> 3, t = tid & 7;
        logit[r][t] = alog[r][fsel[r][t]];
    }
    __syncthreads();
    if (tid < 2) {
        float m = -INFINITY;
#pragma unroll
        for (int t = 0; t < Kv; t++) m = fmaxf(m, logit[tid][t]);
        float e[Kv], ssum = 0.f;
#pragma unroll
        for (int t = 0; t < Kv; t++) { e[t] = expf(logit[tid][t] - m); ssum += e[t]; }
#pragma unroll
        for (int t = 0; t < Kv; t++) attw[tid][t] = e[t] / ssum;
    }
    __syncthreads();

    if (tid < 16) {
        int r = tid >> 3, t = tid & 7;
        int js = fj[r][t];
        gate[(bi0 + r) * Nv + js] = 1.0f;
        att [(bi0 + r) * Nv + js] = attw[r][t];
    }
    if (tid < Dv) {
        int d = tid;
#pragma unroll
        for (int r = 0; r < 2; r++) {
            float cv = 0.f;
#pragma unroll
            for (int t = 0; t < Kv; t++)
                cv = fmaf(attw[r][t], selT[d][r * Cv + fsel[r][t]], cv);
            ctx[(bi0 + r) * Dv + d] = cv;
        }
    }
}

// ---------------------------------------------------------------------------
extern "C" void kernel_launch(void* const* d_in, const int* in_sizes, int n_in,
                              void* d_out, int out_size)
{
    const float* s   = (const float*)d_in[0];
    const float* Wg1 = (const float*)d_in[1];
    const float* bg1 = (const float*)d_in[2];
    const float* Wg2 = (const float*)d_in[3];
    const float* bg2 = (const float*)d_in[4];
    const float* Wa1 = (const float*)d_in[5];
    const float* ba1 = (const float*)d_in[6];
    const float* Wa2 = (const float*)d_in[7];
    const float* ba2 = (const float*)d_in[8];

    float* out  = (float*)d_out;
    float* ctx  = out;
    float* gate = out + Bv * Nv * Dv;
    float* att  = gate + Bv * Nv * Nv;

    cudaFuncSetAttribute(fused_kernel,
                         cudaFuncAttributeMaxDynamicSharedMemorySize, FUS_SMEM);

    fused_kernel<<<ROWS / 2, 256, FUS_SMEM>>>(s, Wg1, bg1, Wg2, bg2,
                                              Wa1, ba1, Wa2, ba2, ctx, gate, att);
}

// round 6
// speedup vs baseline: 4.5970x; 1.1955x over previous
#include <cuda_runtime.h>
#include <cuda_bf16.h>
#include <math.h>

// Problem constants
#define Bv 4
#define Nv 256
#define Dv 128
#define Hv 256
#define Kv 8
#define Cv 12               // candidate count for exact rescore
#define ROWS (Bv * Nv)      // 1024

// Packed bf16 gate weights: [d][hpair] -> {wm_pair, wb_pair}
__device__ uint2 WPK_buf[Dv * (Hv / 2)];   // 16384 uint2

// ---------------------------------------------------------------------------
// f32x2 packed helpers (sm_103a dual fp32 pipe)
// ---------------------------------------------------------------------------
__device__ __forceinline__ void ffma2(unsigned long long& d,
                                      unsigned long long a,
                                      unsigned long long b) {
    asm("fma.rn.f32x2 %0, %1, %2, %0;" : "+l"(d) : "l"(a), "l"(b));
}
__device__ __forceinline__ unsigned long long pack2(float x, float y) {
    unsigned long long r;
    asm("mov.b64 %0, {%1, %2};" : "=l"(r) : "f"(x), "f"(y));
    return r;
}
__device__ __forceinline__ float2 unpack2(unsigned long long v) {
    float2 r;
    asm("mov.b64 {%0, %1}, %2;" : "=f"(r.x), "=f"(r.y) : "l"(v));
    return r;
}

// ---------------------------------------------------------------------------
// MMA helpers
// ---------------------------------------------------------------------------
__device__ __forceinline__ void ldsm4(unsigned* r, unsigned addr) {
    asm volatile("ldmatrix.sync.aligned.m8n8.x4.shared.b16 {%0,%1,%2,%3}, [%4];"
                 : "=r"(r[0]), "=r"(r[1]), "=r"(r[2]), "=r"(r[3]) : "r"(addr));
}
__device__ __forceinline__ void ldsm4t(unsigned* r, unsigned addr) {
    asm volatile("ldmatrix.sync.aligned.m8n8.x4.trans.shared.b16 {%0,%1,%2,%3}, [%4];"
                 : "=r"(r[0]), "=r"(r[1]), "=r"(r[2]), "=r"(r[3]) : "r"(addr));
}
__device__ __forceinline__ void mma16816(float* d, const unsigned* a, unsigned b0, unsigned b1) {
    asm volatile("mma.sync.aligned.m16n8k16.row.col.f32.bf16.bf16.f32 "
                 "{%0,%1,%2,%3}, {%4,%5,%6,%7}, {%8,%9}, {%0,%1,%2,%3};"
                 : "+f"(d[0]), "+f"(d[1]), "+f"(d[2]), "+f"(d[3])
                 : "r"(a[0]), "r"(a[1]), "r"(a[2]), "r"(a[3]), "r"(b0), "r"(b1));
}

// ---------------------------------------------------------------------------
// Prelude: pack gate W_mid/W_bot to bf16 pairs.
// ---------------------------------------------------------------------------
__global__ void pack_kernel(const float* __restrict__ Wg1)
{
    int idx = blockIdx.x * 256 + threadIdx.x;   // 0..16383
    int d  = idx >> 7;
    int hp = idx & 127;
    int h0 = hp * 2;
    float m0 = Wg1[(Dv + d) * Hv + h0];
    float m1 = Wg1[(Dv + d) * Hv + h0 + 1];
    float b0 = Wg1[(2 * Dv + d) * Hv + h0];
    float b1 = Wg1[(2 * Dv + d) * Hv + h0 + 1];
    __nv_bfloat162 mp = __floats2bfloat162_rn(m0, m1);
    __nv_bfloat162 bp = __floats2bfloat162_rn(b0, b1);
    uint2 v;
    v.x = *(unsigned*)&mp;
    v.y = *(unsigned*)&bp;
    WPK_buf[idx] = v;
}

// ---------------------------------------------------------------------------
// Fused kernel: per block (2 rows i0,i0+1 of batch b).
// Pipelined GEMM: double-buffered c tile, build(r+1) overlapped with MMA(r).
// ---------------------------------------------------------------------------
#define SJ 136   // padded bf16 stride for s tile (row = 272B)
#define CH 72    // padded bf16 stride for c tile (row = 144B)
#define TPAD 24  // selT row stride in floats (Cv*2 = 24, 96B rows, 16B aligned)

#define OFS_C     69632           // two c bufs, 18432 each (selT aliases later)
#define OFS_SCORE 106496          // 2 x 256 f32 (partg/parta alias later)
#define OFS_UB    108544          // 2 x 256 f32 (Ug + bg1)
#define OFS_W2    110592          // 256 f32
#define OFS_SI    111616          // 2 x 128 f32
#define OFS_SIB   112640          // 256 x bf16x2 (unsigned)
#define FUS_SMEM  113664

__global__ __launch_bounds__(256, 2) void fused_kernel(
    const float* __restrict__ s,
    const float* __restrict__ Wg1,
    const float* __restrict__ bg1,
    const float* __restrict__ Wg2,
    const float* __restrict__ bg2,
    const float* __restrict__ Wa1,
    const float* __restrict__ ba1,
    const float* __restrict__ Wa2,
    const float* __restrict__ ba2,
    float* __restrict__ ctx,
    float* __restrict__ gate,
    float* __restrict__ att)
{
    extern __shared__ unsigned char dynsm[];
    __nv_bfloat16* s_sm = (__nv_bfloat16*)dynsm;
    float (*selT)[TPAD] = (float (*)[TPAD])(dynsm + OFS_C);    // alias, post-GEMM
    float* score_sm = (float*)(dynsm + OFS_SCORE);             // [2][256]
    float* ub_sm    = (float*)(dynsm + OFS_UB);                // [2][256] Ug+bg1
    float* w2_sm    = (float*)(dynsm + OFS_W2);
    float* si_sm    = (float*)(dynsm + OFS_SI);                // [2][128]
    unsigned* sib_sm = (unsigned*)(dynsm + OFS_SIB);           // [2][128] bf16x2
    // partials overlay score region after selection
    float* partg = score_sm;                                   // [2][Cv][8]
    float* parta = score_sm + 2 * Cv * 8;

    __shared__ float exacts[2][Cv];
    __shared__ float alog[2][Cv];
    __shared__ int   sel[2][Cv];
    __shared__ int   fsel[2][Kv];
    __shared__ int   fj[2][Kv];
    __shared__ float logit[2][Kv];
    __shared__ float attw[2][Kv];

    int bi0 = blockIdx.x * 2;       // global row index (b*Nv + i0)
    int b   = bi0 >> 8;
    int tid = threadIdx.x;
    int lane = tid & 31;
    int warp = tid >> 5;

    // zero this block's gate + att rows
    {
        float4 z = make_float4(0.f, 0.f, 0.f, 0.f);
        float4* gp = (float4*)(gate + bi0 * Nv);
        float4* ap = (float4*)(att  + bi0 * Nv);
        if (tid < 128) { gp[tid] = z; ap[tid] = z; }
    }

    // si + small vectors
    {
        int r = tid >> 7, d = tid & 127;
        float v = s[(bi0 + r) * Dv + d];
        si_sm[r * 128 + d] = v;
        __nv_bfloat16 bv = __float2bfloat16(v);
        __nv_bfloat162 bb = __nv_bfloat162(bv, bv);
        sib_sm[r * 128 + d] = *(unsigned*)&bb;
    }
    w2_sm[tid] = Wg2[tid];
    float wa2_r = Wa2[tid];
    score_sm[tid]       = 0.f;
    score_sm[256 + tid] = 0.f;
    __syncthreads();

    // s_b -> bf16 padded smem (float4 loads, 8B stores)
    {
        const float4* sp4 = (const float4*)(s + b * Nv * Dv);
#pragma unroll
        for (int k = 0; k < 32; k++) {
            int t = k * 256 + tid;            // 0..8191 float4s
            int row = t >> 5;
            int c4  = t & 31;
            float4 v = sp4[t];
            __nv_bfloat162 lo = __floats2bfloat162_rn(v.x, v.y);
            __nv_bfloat162 hi = __floats2bfloat162_rn(v.z, v.w);
            uint2 pk;
            pk.x = *(unsigned*)&lo;
            pk.y = *(unsigned*)&hi;
            *(uint2*)((char*)s_sm + row * 272 + c4 * 8) = pk;
        }
    }

    // inline U for both MLPs, both rows (thread owns h = tid); fold biases in
    float ua0_r, ua1_r;
    {
        int h = tid;
        float ug0 = bg1[h], ug1 = ug0;
        float ua0 = ba1[h], ua1 = ua0;
#pragma unroll 8
        for (int d = 0; d < Dv; d++) {
            float wg = Wg1[d * Hv + h];
            float wa = Wa1[d * Hv + h];
            float s0 = si_sm[d];
            float s1 = si_sm[128 + d];
            ug0 = fmaf(s0, wg, ug0);
            ug1 = fmaf(s1, wg, ug1);
            ua0 = fmaf(s0, wa, ua0);
            ua1 = fmaf(s1, wa, ua1);
        }
        ub_sm[h]       = ug0;
        ub_sm[256 + h] = ug1;
        ua0_r = ua0;
        ua1_r = ua1;
    }

    // ---------------- pipelined GEMM phase ----------------
    const unsigned sbase  = (unsigned)__cvta_generic_to_shared(s_sm);
    const unsigned cbase0 = (unsigned)__cvta_generic_to_shared(dynsm + OFS_C);
    int wm_ = (warp & 3) * 64;
    int wn  = (warp >> 2) * 32;
    int aRow  = wm_ + (lane & 15);
    int aColB = ((lane >> 4) << 3) * 2;
    int bK    = lane & 15;
    int bH    = wn + ((lane >> 4) << 3);

    int bld_d  = tid >> 5;            // thread's d base lane-group (0..7 step over k)
    // build thread mapping: idx = k*256+tid; dd = idx>>5 = k*8 + (tid>>5); hp = tid&31
    int bld_hp = tid & 31;

    // initial build: round 0 (hc=0, ii=0) into buf 0
    {
        unsigned char* cbuf = dynsm + OFS_C;
#pragma unroll
        for (int k = 0; k < 16; k++) {
            int dd = k * 8 + bld_d;
            uint2 wv = WPK_buf[dd * 128 + 0 * 32 + bld_hp];
            __nv_bfloat162 sib = *(__nv_bfloat162*)&sib_sm[0 * 128 + dd];
            __nv_bfloat162 mp = *(__nv_bfloat162*)&wv.x;
            __nv_bfloat162 bp = *(__nv_bfloat162*)&wv.y;
            __nv_bfloat162 c = __hfma2(sib, bp, mp);
            *(unsigned*)(cbuf + dd * 144 + bld_hp * 4) = *(unsigned*)&c;
        }
    }
    __syncthreads();

#pragma unroll 1
    for (int r = 0; r < 8; r++) {
        int hc = r >> 1, ii = r & 1;
        int nxt = r + 1;

        // prefetch W chunk for next round
        uint2 w[16];
        if (nxt < 8) {
            int hcN = nxt >> 1;
#pragma unroll
            for (int k = 0; k < 16; k++) {
                int dd = k * 8 + bld_d;
                w[k] = WPK_buf[dd * 128 + hcN * 32 + bld_hp];
            }
        }

        // MMA on current buffer
        float acc[16][4];
#pragma unroll
        for (int q = 0; q < 16; q++) { acc[q][0]=0.f; acc[q][1]=0.f; acc[q][2]=0.f; acc[q][3]=0.f; }

        unsigned cb = cbase0 + (unsigned)((r & 1) * 18432);
#pragma unroll
        for (int ks = 0; ks < 8; ks++) {
            unsigned a[4][4], bq[2][4];
#pragma unroll
            for (int mt = 0; mt < 4; mt++) {
                unsigned addr = sbase + (unsigned)((aRow + mt * 16) * (SJ * 2) + ks * 32) + aColB;
                ldsm4(a[mt], addr);
            }
#pragma unroll
            for (int nt = 0; nt < 2; nt++) {
                unsigned addr = cb + (unsigned)((ks * 16 + bK) * (CH * 2) + (bH + nt * 16) * 2);
                ldsm4t(bq[nt], addr);
            }
#pragma unroll
            for (int mt = 0; mt < 4; mt++)
#pragma unroll
                for (int n8 = 0; n8 < 4; n8++)
                    mma16816(acc[mt * 4 + n8], a[mt], bq[n8 >> 1][(n8 & 1) * 2], bq[n8 >> 1][(n8 & 1) * 2 + 1]);
        }

        // commit build of next round's c tile
        if (nxt < 8) {
            int iiN = nxt & 1;
            unsigned char* cbuf = dynsm + OFS_C + (nxt & 1) * 18432;
#pragma unroll
            for (int k = 0; k < 16; k++) {
                int dd = k * 8 + bld_d;
                __nv_bfloat162 sib = *(__nv_bfloat162*)&sib_sm[iiN * 128 + dd];
                __nv_bfloat162 mp = *(__nv_bfloat162*)&w[k].x;
                __nv_bfloat162 bp = *(__nv_bfloat162*)&w[k].y;
                __nv_bfloat162 c = __hfma2(sib, bp, mp);
                *(unsigned*)(cbuf + dd * 144 + bld_hp * 4) = *(unsigned*)&c;
            }
        }

        // epilogue: relu + dot W2, quad reduce, accumulate
        {
            int rr = wm_ + (lane >> 2);
            int hb = hc * 64 + wn + (lane & 3) * 2;
            float* ssm = score_sm + ii * 256;
            const float* ubp = ub_sm + ii * 256;
#pragma unroll
            for (int mt = 0; mt < 4; mt++) {
                float p0 = 0.f, p1 = 0.f;
#pragma unroll
                for (int n8 = 0; n8 < 4; n8++) {
                    int h0 = hb + n8 * 8;
                    float u0 = ubp[h0], u1 = ubp[h0 + 1];
                    float w0 = w2_sm[h0], w1 = w2_sm[h0 + 1];
                    const float* A = acc[mt * 4 + n8];
                    p0 = fmaf(fmaxf(A[0] + u0, 0.f), w0, p0);
                    p0 = fmaf(fmaxf(A[1] + u1, 0.f), w1, p0);
                    p1 = fmaf(fmaxf(A[2] + u0, 0.f), w0, p1);
                    p1 = fmaf(fmaxf(A[3] + u1, 0.f), w1, p1);
                }
                p0 += __shfl_xor_sync(0xffffffffu, p0, 1);
                p0 += __shfl_xor_sync(0xffffffffu, p0, 2);
                p1 += __shfl_xor_sync(0xffffffffu, p1, 1);
                p1 += __shfl_xor_sync(0xffffffffu, p1, 2);
                if ((lane & 3) == 0) {
                    atomicAdd(&ssm[rr + mt * 16], p0);
                    atomicAdd(&ssm[rr + mt * 16 + 8], p1);
                }
            }
        }
        __syncthreads();
    }

    // ---------------- selection + rescore phase ----------------
    // approx top-12 per row directly on score_sm (destructive)
    if (warp < 2) {
        int r = warp;
        float* scr = score_sm + r * 256;
        for (int t = 0; t < Cv; t++) {
            float bv = -INFINITY; int bidx = Nv;
#pragma unroll
            for (int k = 0; k < 8; k++) {
                int q = k * 32 + lane;
                float v = scr[q];
                if (v > bv || (v == bv && q < bidx)) { bv = v; bidx = q; }
            }
#pragma unroll
            for (int off = 16; off > 0; off >>= 1) {
                float ov = __shfl_down_sync(0xffffffffu, bv, off);
                int   oi = __shfl_down_sync(0xffffffffu, bidx, off);
                if (ov > bv || (ov == bv && oi < bidx)) { bv = ov; bidx = oi; }
            }
            bidx = __shfl_sync(0xffffffffu, bidx, 0);
            if (lane == 0) { sel[r][t] = bidx; scr[bidx] = -INFINITY; }
            __syncwarp();
        }
    }
    __syncthreads();

    // gather candidate s_j rows into selT (aliases c bufs, dead now)
#pragma unroll
    for (int k = 0; k < 12; k++) {
        int ii = k * 256 + tid;           // 0..3071
        int d  = ii & 127;
        int rc = ii >> 7;                 // 0..23
        int r  = (rc >= Cv) ? 1 : 0;
        int c  = rc - r * Cv;
        selT[d][rc] = s[(b * Nv + sel[r][c]) * Dv + d];
    }
    __syncthreads();

    // fused exact fp32 rescore (gate + att) for all 24 candidates, FFMA2
    int h = tid;
    unsigned long long ag[2][6], aa[2][6];
#pragma unroll
    for (int r = 0; r < 2; r++)
#pragma unroll
        for (int q = 0; q < 6; q++) { ag[r][q] = 0ull; aa[r][q] = 0ull; }

    const float* pgm = Wg1 + Dv * Hv + h;
    const float* pgb = Wg1 + 2 * Dv * Hv + h;
    const float* pam = Wa1 + Dv * Hv + h;
    const float* pab = Wa1 + 2 * Dv * Hv + h;

#pragma unroll 2
    for (int d = 0; d < Dv; d++) {
        float wgm = pgm[d * Hv];
        float wgb = pgb[d * Hv];
        float wam = pam[d * Hv];
        float wab = pab[d * Hv];
        float s0 = si_sm[d], s1 = si_sm[128 + d];
        float cg0s = fmaf(s0, wgb, wgm);
        float cg1s = fmaf(s1, wgb, wgm);
        float ca0s = fmaf(s0, wab, wam);
        float ca1s = fmaf(s1, wab, wam);
        unsigned long long cg0 = pack2(cg0s, cg0s);
        unsigned long long cg1 = pack2(cg1s, cg1s);
        unsigned long long ca0 = pack2(ca0s, ca0s);
        unsigned long long ca1 = pack2(ca1s, ca1s);

        const ulonglong2* rowp = (const ulonglong2*)&selT[d][0];
#pragma unroll
        for (int q = 0; q < 3; q++) {
            ulonglong2 v0 = rowp[q];          // r0 candidates 4q..4q+3
            ffma2(ag[0][q * 2],     v0.x, cg0);
            ffma2(ag[0][q * 2 + 1], v0.y, cg0);
            ffma2(aa[0][q * 2],     v0.x, ca0);
            ffma2(aa[0][q * 2 + 1], v0.y, ca0);
            ulonglong2 v1 = rowp[3 + q];      // r1 candidates
            ffma2(ag[1][q * 2],     v1.x, cg1);
            ffma2(ag[1][q * 2 + 1], v1.y, cg1);
            ffma2(aa[1][q * 2],     v1.x, ca1);
            ffma2(aa[1][q * 2 + 1], v1.y, ca1);
        }
    }

    // relu + dot W2 for both MLPs, warp reduce, stash partials
#pragma unroll
    for (int r = 0; r < 2; r++) {
        float ug = ub_sm[r * 256 + h];            // includes bg1
        float ua = (r == 0) ? ua0_r : ua1_r;      // includes ba1
        float wg = w2_sm[h];
        float wa = wa2_r;
#pragma unroll
        for (int q = 0; q < 6; q++) {
            float2 g2 = unpack2(ag[r][q]);
            float2 a2 = unpack2(aa[r][q]);
#pragma unroll
            for (int half = 0; half < 2; half++) {
                int t = q * 2 + half;
                float gv = half ? g2.y : g2.x;
                float av = half ? a2.y : a2.x;
                float vg = fmaxf(gv + ug, 0.f) * wg;
                float va = fmaxf(av + ua, 0.f) * wa;
#pragma unroll
                for (int off = 16; off > 0; off >>= 1) {
                    vg += __shfl_xor_sync(0xffffffffu, vg, off);
                    va += __shfl_xor_sync(0xffffffffu, va, off);
                }
                if (lane == 0) {
                    partg[(r * Cv + t) * 8 + warp] = vg;
                    parta[(r * Cv + t) * 8 + warp] = va;
                }
            }
        }
    }
    __syncthreads();

    // block sums
    if (tid < 2 * Cv) {
        int r = tid / Cv, t = tid % Cv;
        float sSum = 0.f;
#pragma unroll
        for (int w8 = 0; w8 < 8; w8++) sSum += partg[(r * Cv + t) * 8 + w8];
        exacts[r][t] = sSum + bg2[0];
    } else if (tid >= 64 && tid < 64 + 2 * Cv) {
        int k = tid - 64;
        int r = k / Cv, t = k % Cv;
        float sSum = 0.f;
#pragma unroll
        for (int w8 = 0; w8 < 8; w8++) sSum += parta[(r * Cv + t) * 8 + w8];
        alog[r][t] = sSum + ba2[0];
    }
    __syncthreads();

    // exact top-8 among 12 candidates (tie -> lowest original j)
    if (warp < 2) {
        int r = warp;
        float v = (lane < Cv) ? exacts[r][lane] : -INFINITY;
        int jj  = (lane < Cv) ? sel[r][lane] : (1 << 30);
        int cc  = lane;
        for (int t = 0; t < Kv; t++) {
            float bv = v; int bj = jj; int bc = cc;
#pragma unroll
            for (int off = 16; off > 0; off >>= 1) {
                float ov = __shfl_down_sync(0xffffffffu, bv, off);
                int   oj = __shfl_down_sync(0xffffffffu, bj, off);
                int   oc = __shfl_down_sync(0xffffffffu, bc, off);
                if (ov > bv || (ov == bv && oj < bj)) { bv = ov; bj = oj; bc = oc; }
            }
            bc = __shfl_sync(0xffffffffu, bc, 0);
            bj = __shfl_sync(0xffffffffu, bj, 0);
            if (lane == 0) { fsel[r][t] = bc; fj[r][t] = bj; }
            if (cc == bc) v = -INFINITY;
        }
    }
    __syncthreads();

    if (tid < 16) {
        int r = tid >> 3, t = tid & 7;
        logit[r][t] = alog[r][fsel[r][t]];
    }
    __syncthreads();
    if (tid < 2) {
        float m = -INFINITY;
#pragma unroll
        for (int t = 0; t < Kv; t++) m = fmaxf(m, logit[tid][t]);
        float e[Kv], ssum = 0.f;
#pragma unroll
        for (int t = 0; t < Kv; t++) { e[t] = expf(logit[tid][t] - m); ssum += e[t]; }
#pragma unroll
        for (int t = 0; t < Kv; t++) attw[tid][t] = e[t] / ssum;
    }
    __syncthreads();

    if (tid < 16) {
        int r = tid >> 3, t = tid & 7;
        int js = fj[r][t];
        gate[(bi0 + r) * Nv + js] = 1.0f;
        att [(bi0 + r) * Nv + js] = attw[r][t];
    }
    if (tid < Dv) {
        int d = tid;
#pragma unroll
        for (int r = 0; r < 2; r++) {
            float cv = 0.f;
#pragma unroll
            for (int t = 0; t < Kv; t++)
                cv = fmaf(attw[r][t], selT[d][r * Cv + fsel[r][t]], cv);
            ctx[(bi0 + r) * Dv + d] = cv;
        }
    }
}

// ---------------------------------------------------------------------------
extern "C" void kernel_launch(void* const* d_in, const int* in_sizes, int n_in,
                              void* d_out, int out_size)
{
    const float* s   = (const float*)d_in[0];
    const float* Wg1 = (const float*)d_in[1];
    const float* bg1 = (const float*)d_in[2];
    const float* Wg2 = (const float*)d_in[3];
    const float* bg2 = (const float*)d_in[4];
    const float* Wa1 = (const float*)d_in[5];
    const float* ba1 = (const float*)d_in[6];
    const float* Wa2 = (const float*)d_in[7];
    const float* ba2 = (const float*)d_in[8];

    float* out  = (float*)d_out;
    float* ctx  = out;
    float* gate = out + Bv * Nv * Dv;
    float* att  = gate + Bv * Nv * Nv;

    cudaFuncSetAttribute(fused_kernel,
                         cudaFuncAttributeMaxDynamicSharedMemorySize, FUS_SMEM);

    pack_kernel<<<64, 256>>>(Wg1);
    fused_kernel<<<ROWS / 2, 256, FUS_SMEM>>>(s, Wg1, bg1, Wg2, bg2,
                                              Wa1, ba1, Wa2, ba2, ctx, gate, att);
}

// round 9
// speedup vs baseline: 4.8629x; 1.0579x over previous
#include <cuda_runtime.h>
#include <cuda_bf16.h>
#include <math.h>

// Problem constants
#define Bv 4
#define Nv 256
#define Dv 128
#define Hv 256
#define Kv 8
#define Cv 12
#define ROWS (Bv * Nv)      // 1024
#define TPAD 24

// Packed bf16 gate weights: [d][hpair] -> {wm_pair, wb_pair}
__device__ uint2 WPK_buf[Dv * (Hv / 2)];   // 16384 uint2

// ---------------------------------------------------------------------------
// f32x2 packed helpers (sm_103a dual fp32 pipe)
// ---------------------------------------------------------------------------
__device__ __forceinline__ void ffma2(unsigned long long& d,
                                      unsigned long long a,
                                      unsigned long long b) {
    asm("fma.rn.f32x2 %0, %1, %2, %0;" : "+l"(d) : "l"(a), "l"(b));
}
__device__ __forceinline__ unsigned long long pack2(float x, float y) {
    unsigned long long r;
    asm("mov.b64 %0, {%1, %2};" : "=l"(r) : "f"(x), "f"(y));
    return r;
}
__device__ __forceinline__ float2 unpack2(unsigned long long v) {
    float2 r;
    asm("mov.b64 {%0, %1}, %2;" : "=f"(r.x), "=f"(r.y) : "l"(v));
    return r;
}

// ---------------------------------------------------------------------------
// MMA helpers
// ---------------------------------------------------------------------------
__device__ __forceinline__ void ldsm4(unsigned* r, unsigned addr) {
    asm volatile("ldmatrix.sync.aligned.m8n8.x4.shared.b16 {%0,%1,%2,%3}, [%4];"
                 : "=r"(r[0]), "=r"(r[1]), "=r"(r[2]), "=r"(r[3]) : "r"(addr));
}
__device__ __forceinline__ void ldsm4t(unsigned* r, unsigned addr) {
    asm volatile("ldmatrix.sync.aligned.m8n8.x4.trans.shared.b16 {%0,%1,%2,%3}, [%4];"
                 : "=r"(r[0]), "=r"(r[1]), "=r"(r[2]), "=r"(r[3]) : "r"(addr));
}
__device__ __forceinline__ void mma16816(float* d, const unsigned* a, unsigned b0, unsigned b1) {
    asm volatile("mma.sync.aligned.m16n8k16.row.col.f32.bf16.bf16.f32 "
                 "{%0,%1,%2,%3}, {%4,%5,%6,%7}, {%8,%9}, {%0,%1,%2,%3};"
                 : "+f"(d[0]), "+f"(d[1]), "+f"(d[2]), "+f"(d[3])
                 : "r"(a[0]), "r"(a[1]), "r"(a[2]), "r"(a[3]), "r"(b0), "r"(b1));
}

// ---------------------------------------------------------------------------
// Prelude: pack gate W_mid/W_bot to bf16 pairs.
// ---------------------------------------------------------------------------
__global__ void pack_kernel(const float* __restrict__ Wg1)
{
    int idx = blockIdx.x * 256 + threadIdx.x;   // 0..16383
    int d  = idx >> 7;
    int hp = idx & 127;
    int h0 = hp * 2;
    float m0 = Wg1[(Dv + d) * Hv + h0];
    float m1 = Wg1[(Dv + d) * Hv + h0 + 1];
    float b0 = Wg1[(2 * Dv + d) * Hv + h0];
    float b1 = Wg1[(2 * Dv + d) * Hv + h0 + 1];
    __nv_bfloat162 mp = __floats2bfloat162_rn(m0, m1);
    __nv_bfloat162 bp = __floats2bfloat162_rn(b0, b1);
    uint2 v;
    v.x = *(unsigned*)&mp;
    v.y = *(unsigned*)&bp;
    WPK_buf[idx] = v;
}

// ---------------------------------------------------------------------------
// smem layout
// ---------------------------------------------------------------------------
#define SJ 136   // padded bf16 stride for s tile (row = 272B)
#define CH 72    // padded bf16 stride for c tile (row = 144B)

#define OFS_A     0               // 69632: s tile [256][SJ] bf16
#define OFS_C     69632           // 2 c bufs x 18432; aliased post-GEMM:
                                  //   +0     : part  [2][2][256] f32 (8KB)
                                  //   +8192  : score [2][256] f32   (2KB)
                                  //   +12288 : selT  [128][TPAD] f32 (12KB)
                                  //   +24576 : partg [2][Cv][8] f32 (768B)
                                  //   +25344 : parta [2][Cv][8] f32 (768B)
#define OFS_UB    106496          // 2 x 256 f32 (Ug + bg1)
#define OFS_W2    108544          // 256 f32
#define OFS_SI    109568          // 2 x 128 f32
#define OFS_SIB   110592          // 256 uint (bf16x2, dup halves)
#define FUS_SMEM  111616

__global__ __launch_bounds__(256, 2) void fused_kernel(
    const float* __restrict__ s,
    const float* __restrict__ Wg1,
    const float* __restrict__ bg1,
    const float* __restrict__ Wg2,
    const float* __restrict__ bg2,
    const float* __restrict__ Wa1,
    const float* __restrict__ ba1,
    const float* __restrict__ Wa2,
    const float* __restrict__ ba2,
    float* __restrict__ ctx,
    float* __restrict__ gate,
    float* __restrict__ att)
{
    extern __shared__ unsigned char dynsm[];
    __nv_bfloat16* s_sm = (__nv_bfloat16*)dynsm;
    float* ub_sm    = (float*)(dynsm + OFS_UB);
    float* w2_sm    = (float*)(dynsm + OFS_W2);
    float* si_sm    = (float*)(dynsm + OFS_SI);
    unsigned* sib_sm = (unsigned*)(dynsm + OFS_SIB);
    // post-GEMM aliases of the C region
    float* part_sm  = (float*)(dynsm + OFS_C);              // [2][2][256]
    float* score_sm = (float*)(dynsm + OFS_C + 8192);       // [2][256]
    float (*selT)[TPAD] = (float (*)[TPAD])(dynsm + OFS_C + 12288);
    float* partg = (float*)(dynsm + OFS_C + 24576);         // [2][Cv][8]
    float* parta = (float*)(dynsm + OFS_C + 25344);

    __shared__ float exacts[2][Cv];
    __shared__ float alog[2][Cv];
    __shared__ int   sel[2][Cv];
    __shared__ int   fsel[2][Kv];
    __shared__ int   fj[2][Kv];
    __shared__ float logit[2][Kv];
    __shared__ float attw[2][Kv];

    int bi0 = blockIdx.x * 2;       // global row index (b*Nv + i0)
    int b   = bi0 >> 8;
    int tid = threadIdx.x;
    int lane = tid & 31;
    int warp = tid >> 5;

    // zero this block's gate + att rows
    {
        float4 z = make_float4(0.f, 0.f, 0.f, 0.f);
        float4* gp = (float4*)(gate + bi0 * Nv);
        float4* ap = (float4*)(att  + bi0 * Nv);
        if (tid < 128) { gp[tid] = z; ap[tid] = z; }
    }

    // si + small vectors
    {
        int r = tid >> 7, d = tid & 127;
        float v = s[(bi0 + r) * Dv + d];
        si_sm[r * 128 + d] = v;
        __nv_bfloat16 bv = __float2bfloat16(v);
        __nv_bfloat162 bb = __nv_bfloat162(bv, bv);
        sib_sm[r * 128 + d] = *(unsigned*)&bb;
    }
    w2_sm[tid] = Wg2[tid];
    float wa2_r = Wa2[tid];
    __syncthreads();

    // s_b -> bf16 padded smem (float4 loads, 8B stores)
    {
        const float4* sp4 = (const float4*)(s + b * Nv * Dv);
#pragma unroll
        for (int k = 0; k < 32; k++) {
            int t = k * 256 + tid;            // 0..8191 float4s
            int row = t >> 5;
            int c4  = t & 31;
            float4 v = sp4[t];
            __nv_bfloat162 lo = __floats2bfloat162_rn(v.x, v.y);
            __nv_bfloat162 hi = __floats2bfloat162_rn(v.z, v.w);
            uint2 pk;
            pk.x = *(unsigned*)&lo;
            pk.y = *(unsigned*)&hi;
            *(uint2*)((char*)s_sm + row * 272 + c4 * 8) = pk;
        }
    }

    // inline U for both MLPs, both rows (thread owns h = tid); fold biases in
    float ua0_r, ua1_r;
    {
        int h = tid;
        float ug0 = bg1[h], ug1 = ug0;
        float ua0 = ba1[h], ua1 = ua0;
#pragma unroll 8
        for (int d = 0; d < Dv; d++) {
            float wg = Wg1[d * Hv + h];
            float wa = Wa1[d * Hv + h];
            float s0 = si_sm[d];
            float s1 = si_sm[128 + d];
            ug0 = fmaf(s0, wg, ug0);
            ug1 = fmaf(s1, wg, ug1);
            ua0 = fmaf(s0, wa, ua0);
            ua1 = fmaf(s1, wa, ua1);
        }
        ub_sm[h]       = ug0;
        ub_sm[256 + h] = ug1;
        ua0_r = ua0;
        ua1_r = ua1;
    }

    // ---------------- pipelined GEMM phase ----------------
    const unsigned sbase  = (unsigned)__cvta_generic_to_shared(s_sm);
    const unsigned cbase0 = (unsigned)__cvta_generic_to_shared(dynsm + OFS_C);
    int wm_ = (warp & 3) * 64;
    int wn  = (warp >> 2) * 32;
    int aRow  = wm_ + (lane & 15);
    int aColB = ((lane >> 4) << 3) * 2;
    int bK    = lane & 15;
    int bH    = wn + ((lane >> 4) << 3);

    int bld_d  = tid >> 5;
    int bld_hp = tid & 31;

    // per-thread running score partials (quad-lane h-slices)
    float sreg[2][4][2];
#pragma unroll
    for (int ii = 0; ii < 2; ii++)
#pragma unroll
        for (int mt = 0; mt < 4; mt++) { sreg[ii][mt][0] = 0.f; sreg[ii][mt][1] = 0.f; }

    // initial build: round 0 (hc=0, ii=0) into buf 0
    {
        unsigned char* cbuf = dynsm + OFS_C;
#pragma unroll
        for (int k = 0; k < 16; k++) {
            int dd = k * 8 + bld_d;
            uint2 wv = WPK_buf[dd * 128 + 0 * 32 + bld_hp];
            __nv_bfloat162 sib = *(__nv_bfloat162*)&sib_sm[0 * 128 + dd];
            __nv_bfloat162 mp = *(__nv_bfloat162*)&wv.x;
            __nv_bfloat162 bp = *(__nv_bfloat162*)&wv.y;
            __nv_bfloat162 c = __hfma2(sib, bp, mp);
            *(unsigned*)(cbuf + dd * 144 + bld_hp * 4) = *(unsigned*)&c;
        }
    }
    __syncthreads();

#pragma unroll 1
    for (int r = 0; r < 8; r++) {
        int hc = r >> 1, ii = r & 1;
        int nxt = r + 1;

        // prefetch first half of W chunk for next round (regs)
        uint2 w[8];
        if (nxt < 8) {
            int hcN = nxt >> 1;
#pragma unroll
            for (int k = 0; k < 8; k++) {
                int dd = k * 8 + bld_d;
                w[k] = WPK_buf[dd * 128 + hcN * 32 + bld_hp];
            }
        }

        // MMA on current buffer
        float acc[16][4];
#pragma unroll
        for (int q = 0; q < 16; q++) { acc[q][0]=0.f; acc[q][1]=0.f; acc[q][2]=0.f; acc[q][3]=0.f; }

        unsigned cb = cbase0 + (unsigned)((r & 1) * 18432);
#pragma unroll
        for (int ks = 0; ks < 8; ks++) {
            unsigned a[4][4], bq[2][4];
#pragma unroll
            for (int mt = 0; mt < 4; mt++) {
                unsigned addr = sbase + (unsigned)((aRow + mt * 16) * (SJ * 2) + ks * 32) + aColB;
                ldsm4(a[mt], addr);
            }
#pragma unroll
            for (int nt = 0; nt < 2; nt++) {
                unsigned addr = cb + (unsigned)((ks * 16 + bK) * (CH * 2) + (bH + nt * 16) * 2);
                ldsm4t(bq[nt], addr);
            }
#pragma unroll
            for (int mt = 0; mt < 4; mt++)
#pragma unroll
                for (int n8 = 0; n8 < 4; n8++)
                    mma16816(acc[mt * 4 + n8], a[mt], bq[n8 >> 1][(n8 & 1) * 2], bq[n8 >> 1][(n8 & 1) * 2 + 1]);
        }

        // commit build of next round's c tile (first 8 from regs, last 8 inline)
        if (nxt < 8) {
            int iiN = nxt & 1;
            int hcN = nxt >> 1;
            unsigned char* cbuf = dynsm + OFS_C + (nxt & 1) * 18432;
#pragma unroll
            for (int k = 0; k < 8; k++) {
                int dd = k * 8 + bld_d;
                __nv_bfloat162 sib = *(__nv_bfloat162*)&sib_sm[iiN * 128 + dd];
                __nv_bfloat162 mp = *(__nv_bfloat162*)&w[k].x;
                __nv_bfloat162 bp = *(__nv_bfloat162*)&w[k].y;
                __nv_bfloat162 c = __hfma2(sib, bp, mp);
                *(unsigned*)(cbuf + dd * 144 + bld_hp * 4) = *(unsigned*)&c;
            }
#pragma unroll
            for (int k = 8; k < 16; k++) {
                int dd = k * 8 + bld_d;
                uint2 wv = WPK_buf[dd * 128 + hcN * 32 + bld_hp];
                __nv_bfloat162 sib = *(__nv_bfloat162*)&sib_sm[iiN * 128 + dd];
                __nv_bfloat162 mp = *(__nv_bfloat162*)&wv.x;
                __nv_bfloat162 bp = *(__nv_bfloat162*)&wv.y;
                __nv_bfloat162 c = __hfma2(sib, bp, mp);
                *(unsigned*)(cbuf + dd * 144 + bld_hp * 4) = *(unsigned*)&c;
            }
        }

        // epilogue: relu + dot W2 into register partials (no shfl/atomics)
        {
            int hb = hc * 64 + wn + (lane & 3) * 2;
            const float2* u2p = (const float2*)(ub_sm + ii * 256);
            const float2* w2p = (const float2*)w2_sm;
            float2 uu[4], ww[4];
#pragma unroll
            for (int n8 = 0; n8 < 4; n8++) {
                uu[n8] = u2p[(hb + n8 * 8) >> 1];
                ww[n8] = w2p[(hb + n8 * 8) >> 1];
            }
#pragma unroll
            for (int mt = 0; mt < 4; mt++) {
                float p0 = sreg[ii][mt][0];
                float p1 = sreg[ii][mt][1];
#pragma unroll
                for (int n8 = 0; n8 < 4; n8++) {
                    const float* A = acc[mt * 4 + n8];
                    p0 = fmaf(fmaxf(A[0] + uu[n8].x, 0.f), ww[n8].x, p0);
                    p0 = fmaf(fmaxf(A[1] + uu[n8].y, 0.f), ww[n8].y, p0);
                    p1 = fmaf(fmaxf(A[2] + uu[n8].x, 0.f), ww[n8].x, p1);
                    p1 = fmaf(fmaxf(A[3] + uu[n8].y, 0.f), ww[n8].y, p1);
                }
                sreg[ii][mt][0] = p0;
                sreg[ii][mt][1] = p1;
            }
        }
        __syncthreads();
    }

    // final reduction: quad-reduce sreg, write per-nwarp parts (alias C, now dead)
    {
        int nw = wn >> 5;   // 0 or 1
#pragma unroll
        for (int ii = 0; ii < 2; ii++)
#pragma unroll
            for (int mt = 0; mt < 4; mt++)
#pragma unroll
                for (int half = 0; half < 2; half++) {
                    float v = sreg[ii][mt][half];
                    v += __shfl_xor_sync(0xffffffffu, v, 1);
                    v += __shfl_xor_sync(0xffffffffu, v, 2);
                    if ((lane & 3) == 0) {
                        int j = wm_ + (lane >> 2) + mt * 16 + half * 8;
                        part_sm[(ii * 2 + nw) * 256 + j] = v;
                    }
                }
    }
    __syncthreads();
    {
        float b2v = bg2[0];
        score_sm[tid]       = part_sm[tid]        + part_sm[256 + tid] + b2v;
        score_sm[256 + tid] = part_sm[512 + tid]  + part_sm[768 + tid] + b2v;
    }
    __syncthreads();

    // ---------------- selection + rescore phase ----------------
    // approx top-12 per row directly on score_sm (destructive)
    if (warp < 2) {
        int r = warp;
        float* scr = score_sm + r * 256;
        for (int t = 0; t < Cv; t++) {
            float bv = -INFINITY; int bidx = Nv;
#pragma unroll
            for (int k = 0; k < 8; k++) {
                int q = k * 32 + lane;
                float v = scr[q];
                if (v > bv || (v == bv && q < bidx)) { bv = v; bidx = q; }
            }
#pragma unroll
            for (int off = 16; off > 0; off >>= 1) {
                float ov = __shfl_down_sync(0xffffffffu, bv, off);
                int   oi = __shfl_down_sync(0xffffffffu, bidx, off);
                if (ov > bv || (ov == bv && oi < bidx)) { bv = ov; bidx = oi; }
            }
            bidx = __shfl_sync(0xffffffffu, bidx, 0);
            if (lane == 0) { sel[r][t] = bidx; scr[bidx] = -INFINITY; }
            __syncwarp();
        }
    }
    __syncthreads();

    // gather candidate s_j rows into selT
#pragma unroll
    for (int k = 0; k < 12; k++) {
        int ii = k * 256 + tid;           // 0..3071
        int d  = ii & 127;
        int rc = ii >> 7;                 // 0..23
        int r  = (rc >= Cv) ? 1 : 0;
        int c  = rc - r * Cv;
        selT[d][rc] = s[(b * Nv + sel[r][c]) * Dv + d];
    }
    __syncthreads();

    // fused exact fp32 rescore (gate + att) for all 24 candidates, FFMA2
    int h = tid;
    unsigned long long ag[2][6], aa[2][6];
#pragma unroll
    for (int r = 0; r < 2; r++)
#pragma unroll
        for (int q = 0; q < 6; q++) { ag[r][q] = 0ull; aa[r][q] = 0ull; }

    const float* pgm = Wg1 + Dv * Hv + h;
    const float* pgb = Wg1 + 2 * Dv * Hv + h;
    const float* pam = Wa1 + Dv * Hv + h;
    const float* pab = Wa1 + 2 * Dv * Hv + h;

#pragma unroll 2
    for (int d = 0; d < Dv; d++) {
        float wgm = pgm[d * Hv];
        float wgb = pgb[d * Hv];
        float wam = pam[d * Hv];
        float wab = pab[d * Hv];
        float s0 = si_sm[d], s1 = si_sm[128 + d];
        float cg0s = fmaf(s0, wgb, wgm);
        float cg1s = fmaf(s1, wgb, wgm);
        float ca0s = fmaf(s0, wab, wam);
        float ca1s = fmaf(s1, wab, wam);
        unsigned long long cg0 = pack2(cg0s, cg0s);
        unsigned long long cg1 = pack2(cg1s, cg1s);
        unsigned long long ca0 = pack2(ca0s, ca0s);
        unsigned long long ca1 = pack2(ca1s, ca1s);

        const ulonglong2* rowp = (const ulonglong2*)&selT[d][0];
#pragma unroll
        for (int q = 0; q < 3; q++) {
            ulonglong2 v0 = rowp[q];
            ffma2(ag[0][q * 2],     v0.x, cg0);
            ffma2(ag[0][q * 2 + 1], v0.y, cg0);
            ffma2(aa[0][q * 2],     v0.x, ca0);
            ffma2(aa[0][q * 2 + 1], v0.y, ca0);
            ulonglong2 v1 = rowp[3 + q];
            ffma2(ag[1][q * 2],     v1.x, cg1);
            ffma2(ag[1][q * 2 + 1], v1.y, cg1);
            ffma2(aa[1][q * 2],     v1.x, ca1);
            ffma2(aa[1][q * 2 + 1], v1.y, ca1);
        }
    }

    // relu + dot W2 for both MLPs, warp reduce, stash partials
#pragma unroll
    for (int r = 0; r < 2; r++) {
        float ug = ub_sm[r * 256 + h];            // includes bg1
        float ua = (r == 0) ? ua0_r : ua1_r;      // includes ba1
        float wg = w2_sm[h];
        float wa = wa2_r;
#pragma unroll
        for (int q = 0; q < 6; q++) {
            float2 g2 = unpack2(ag[r][q]);
            float2 a2 = unpack2(aa[r][q]);
#pragma unroll
            for (int half = 0; half < 2; half++) {
                int t = q * 2 + half;
                float gv = half ? g2.y : g2.x;
                float av = half ? a2.y : a2.x;
                float vg = fmaxf(gv + ug, 0.f) * wg;
                float va = fmaxf(av + ua, 0.f) * wa;
#pragma unroll
                for (int off = 16; off > 0; off >>= 1) {
                    vg += __shfl_xor_sync(0xffffffffu, vg, off);
                    va += __shfl_xor_sync(0xffffffffu, va, off);
                }
                if (lane == 0) {
                    partg[(r * Cv + t) * 8 + warp] = vg;
                    parta[(r * Cv + t) * 8 + warp] = va;
                }
            }
        }
    }
    __syncthreads();

    // block sums
    if (tid < 2 * Cv) {
        int r = tid / Cv, t = tid % Cv;
        float sSum = 0.f;
#pragma unroll
        for (int w8 = 0; w8 < 8; w8++) sSum += partg[(r * Cv + t) * 8 + w8];
        exacts[r][t] = sSum + bg2[0];
    } else if (tid >= 64 && tid < 64 + 2 * Cv) {
        int k = tid - 64;
        int r = k / Cv, t = k % Cv;
        float sSum = 0.f;
#pragma unroll
        for (int w8 = 0; w8 < 8; w8++) sSum += parta[(r * Cv + t) * 8 + w8];
        alog[r][t] = sSum + ba2[0];
    }
    __syncthreads();

    // exact top-8 among 12 candidates (tie -> lowest original j)
    if (warp < 2) {
        int r = warp;
        float v = (lane < Cv) ? exacts[r][lane] : -INFINITY;
        int jj  = (lane < Cv) ? sel[r][lane] : (1 << 30);
        int cc  = lane;
        for (int t = 0; t < Kv; t++) {
            float bv = v; int bj = jj; int bc = cc;
#pragma unroll
            for (int off = 16; off > 0; off >>= 1) {
                float ov = __shfl_down_sync(0xffffffffu, bv, off);
                int   oj = __shfl_down_sync(0xffffffffu, bj, off);
                int   oc = __shfl_down_sync(0xffffffffu, bc, off);
                if (ov > bv || (ov == bv && oj < bj)) { bv = ov; bj = oj; bc = oc; }
            }
            bc = __shfl_sync(0xffffffffu, bc, 0);
            bj = __shfl_sync(0xffffffffu, bj, 0);
            if (lane == 0) { fsel[r][t] = bc; fj[r][t] = bj; }
            if (cc == bc) v = -INFINITY;
        }
    }
    __syncthreads();

    if (tid < 16) {
        int r = tid >> 3, t = tid & 7;
        logit[r][t] = alog[r][fsel[r][t]];
    }
    __syncthreads();
    if (tid < 2) {
        float m = -INFINITY;
#pragma unroll
        for (int t = 0; t < Kv; t++) m = fmaxf(m, logit[tid][t]);
        float e[Kv], ssum = 0.f;
#pragma unroll
        for (int t = 0; t < Kv; t++) { e[t] = expf(logit[tid][t] - m); ssum += e[t]; }
#pragma unroll
        for (int t = 0; t < Kv; t++) attw[tid][t] = e[t] / ssum;
    }
    __syncthreads();

    if (tid < 16) {
        int r = tid >> 3, t = tid & 7;
        int js = fj[r][t];
        gate[(bi0 + r) * Nv + js] = 1.0f;
        att [(bi0 + r) * Nv + js] = attw[r][t];
    }
    if (tid < Dv) {
        int d = tid;
#pragma unroll
        for (int r = 0; r < 2; r++) {
            float cv = 0.f;
#pragma unroll
            for (int t = 0; t < Kv; t++)
                cv = fmaf(attw[r][t], selT[d][r * Cv + fsel[r][t]], cv);
            ctx[(bi0 + r) * Dv + d] = cv;
        }
    }
}

// ---------------------------------------------------------------------------
extern "C" void kernel_launch(void* const* d_in, const int* in_sizes, int n_in,
                              void* d_out, int out_size)
{
    const float* s   = (const float*)d_in[0];
    const float* Wg1 = (const float*)d_in[1];
    const float* bg1 = (const float*)d_in[2];
    const float* Wg2 = (const float*)d_in[3];
    const float* bg2 = (const float*)d_in[4];
    const float* Wa1 = (const float*)d_in[5];
    const float* ba1 = (const float*)d_in[6];
    const float* Wa2 = (const float*)d_in[7];
    const float* ba2 = (const float*)d_in[8];

    float* out  = (float*)d_out;
    float* ctx  = out;
    float* gate = out + Bv * Nv * Dv;
    float* att  = gate + Bv * Nv * Nv;

    cudaFuncSetAttribute(fused_kernel,
                         cudaFuncAttributeMaxDynamicSharedMemorySize, FUS_SMEM);

    pack_kernel<<<64, 256>>>(Wg1);
    fused_kernel<<<ROWS / 2, 256, FUS_SMEM>>>(s, Wg1, bg1, Wg2, bg2,
                                              Wa1, ba1, Wa2, ba2, ctx, gate, att);
}